// round 10
// baseline (speedup 1.0000x reference)
#include <cuda_runtime.h>
#include <math.h>

// ---------------------------------------------------------------------------
// Problem constants (fixed shapes from setup_inputs)
// ---------------------------------------------------------------------------
#define Bc   8
#define Nc   2048
#define Dc   768
#define Hc   12
#define DHc  64
#define Mc   256
#define BHc  (Bc * Hc)      // 96
#define BHNc (BHc * Nc)     // 196608
#define BNc  (Bc * Nc)      // 16384

#define DNf    0.3535533905932738f   // 64^-0.25
#define DN2f   0.125f                // DNf^2
#define RATIOf 0.0625f               // 256^-0.5
#define EPSf   1e-4f

// ---------------------------------------------------------------------------
// Device scratch (static globals -> no runtime allocation)
// ---------------------------------------------------------------------------
__device__ float g_q   [(size_t)BHNc * DHc];   // [bh][n][64]
__device__ float g_k   [(size_t)BHNc * DHc];
__device__ float g_v   [(size_t)BHNc * DHc];
__device__ float g_qp  [(size_t)BHNc * Mc];    // [bh*N+n][256]
__device__ float g_kp  [(size_t)BHNc * Mc];
__device__ float g_ctx [(size_t)BHc * Mc * DHc];
__device__ float g_ksum[(size_t)BHc * Mc];
__device__ float g_kpart[(size_t)BHc * 16];
__device__ float g_kmax[(size_t)BHc];
__device__ float g_dinv[(size_t)BHNc];
__device__ float g_attn[(size_t)BNc * Dc];     // [b*N+n][768]

// ---------------------------------------------------------------------------
// Generic NT SGEMM:  C = alpha * (A @ W^T) + bias
//   A   : [Mrows x K]  row-major (Mrows = gridDim.y*128, divisible)
//   W   : [Ncols x K]  row-major (Ncols = gridDim.x*128, divisible)
//   K multiple of 16.
//   headsplit=1 : QKV write into [bh][n][64] layout
//   headsplit=0 : plain row-major [row*Ncols + col]
// Block: 256 threads, 128x128 tile, 8x8 per thread.
// ---------------------------------------------------------------------------
__global__ void __launch_bounds__(256)
sgemm_nt(const float* __restrict__ A,
         const float* __restrict__ Wm,
         const float* __restrict__ bias,
         float* __restrict__ Cout,
         int K, int Ncols, float alpha, int headsplit)
{
    __shared__ float As[16][128];
    __shared__ float Bs[16][128];

    const int tid = threadIdx.x;
    const int tx  = tid & 15;
    const int ty  = tid >> 4;
    const int rowBase = blockIdx.y * 128;
    const int colBase = blockIdx.x * 128;

    float acc[8][8];
#pragma unroll
    for (int i = 0; i < 8; i++)
#pragma unroll
        for (int j = 0; j < 8; j++) acc[i][j] = 0.f;

    for (int k0 = 0; k0 < K; k0 += 16) {
        // 512 float4 per operand tile, 2 per thread, transpose into smem
        for (int f = tid; f < 512; f += 256) {
            int r  = f >> 2;
            int kc = (f & 3) << 2;
            float4 va = *(const float4*)&A [(size_t)(rowBase + r) * K + k0 + kc];
            As[kc + 0][r] = va.x; As[kc + 1][r] = va.y;
            As[kc + 2][r] = va.z; As[kc + 3][r] = va.w;
            float4 vb = *(const float4*)&Wm[(size_t)(colBase + r) * K + k0 + kc];
            Bs[kc + 0][r] = vb.x; Bs[kc + 1][r] = vb.y;
            Bs[kc + 2][r] = vb.z; Bs[kc + 3][r] = vb.w;
        }
        __syncthreads();

#pragma unroll
        for (int kk = 0; kk < 16; kk++) {
            float a[8], b[8];
            *(float4*)(a)     = *(const float4*)&As[kk][ty * 8];
            *(float4*)(a + 4) = *(const float4*)&As[kk][ty * 8 + 4];
            *(float4*)(b)     = *(const float4*)&Bs[kk][tx * 8];
            *(float4*)(b + 4) = *(const float4*)&Bs[kk][tx * 8 + 4];
#pragma unroll
            for (int i = 0; i < 8; i++)
#pragma unroll
                for (int j = 0; j < 8; j++)
                    acc[i][j] += a[i] * b[j];
        }
        __syncthreads();
    }

    float bj[8];
#pragma unroll
    for (int j = 0; j < 8; j++)
        bj[j] = bias ? bias[colBase + tx * 8 + j] : 0.f;

#pragma unroll
    for (int i = 0; i < 8; i++) {
        const int row = rowBase + ty * 8 + i;
#pragma unroll
        for (int j = 0; j < 8; j++) {
            const int col = colBase + tx * 8 + j;
            const float v = acc[i][j] * alpha + bj[j];
            if (headsplit) {
                const int bb = row >> 11;          // N = 2048
                const int n  = row & 2047;
                const int h  = col >> 6;           // head dim 64
                const int dd = col & 63;
                Cout[(((size_t)(bb * Hc + h) * Nc + n) << 6) + dd] = v;
            } else {
                Cout[(size_t)row * Ncols + col] = v;
            }
        }
    }
}

// ---------------------------------------------------------------------------
// Per-head max of raw key features, two-stage
// ---------------------------------------------------------------------------
__global__ void kmax_stage1()
{
    const int bh   = blockIdx.y;
    const int part = blockIdx.x;                  // 16 parts
    const int chunk = Nc * Mc / 16;               // 32768
    const size_t base = (size_t)bh * Nc * Mc + (size_t)part * chunk;
    float m = -3.0e38f;
    for (int i = threadIdx.x; i < chunk; i += 256)
        m = fmaxf(m, g_kp[base + i]);
#pragma unroll
    for (int o = 16; o > 0; o >>= 1)
        m = fmaxf(m, __shfl_xor_sync(0xffffffffu, m, o));
    __shared__ float sm[8];
    if ((threadIdx.x & 31) == 0) sm[threadIdx.x >> 5] = m;
    __syncthreads();
    if (threadIdx.x == 0) {
        float mm = sm[0];
#pragma unroll
        for (int i = 1; i < 8; i++) mm = fmaxf(mm, sm[i]);
        g_kpart[bh * 16 + part] = mm;
    }
}

__global__ void kmax_stage2()
{
    const int bh = threadIdx.x;                   // 96 threads
    if (bh >= BHc) return;
    float m = -3.0e38f;
#pragma unroll
    for (int i = 0; i < 16; i++) m = fmaxf(m, g_kpart[bh * 16 + i]);
    g_kmax[bh] = m;
}

// ---------------------------------------------------------------------------
// FAVOR+ feature finalize: phi = ratio*(exp(xp - diag - m) + eps), in place.
// One block (256 thr) per row; thread t owns feature m=t.
// ---------------------------------------------------------------------------
__global__ void __launch_bounds__(256)
finalize_phi(const float* __restrict__ qk,   // g_q or g_k, [row][64]
             float* __restrict__ phi,        // g_qp or g_kp, [row][256]
             int isQuery)
{
    const int r  = blockIdx.x;                    // [0, BHNc)
    const int t  = threadIdx.x;
    const int bh = r >> 11;

    __shared__ float sA[8];
    __shared__ float sB[8];

    // diag = 0.5 * dn^2 * ||q_row||^2
    float xv = (t < DHc) ? qk[(size_t)r * DHc + t] : 0.f;
    float sq = xv * xv;
#pragma unroll
    for (int o = 16; o > 0; o >>= 1)
        sq += __shfl_xor_sync(0xffffffffu, sq, o);
    if ((t & 31) == 0) sA[t >> 5] = sq;

    const float xp = phi[(size_t)r * Mc + t];

    float mx;
    if (isQuery) {
        float m = xp;
#pragma unroll
        for (int o = 16; o > 0; o >>= 1)
            m = fmaxf(m, __shfl_xor_sync(0xffffffffu, m, o));
        if ((t & 31) == 0) sB[t >> 5] = m;
        __syncthreads();
        mx = sB[0];
#pragma unroll
        for (int i = 1; i < 8; i++) mx = fmaxf(mx, sB[i]);
    } else {
        __syncthreads();
        mx = g_kmax[bh];
    }

    float ssum = sA[0];
#pragma unroll
    for (int i = 1; i < 8; i++) ssum += sA[i];
    const float diag = 0.5f * DN2f * ssum;

    phi[(size_t)r * Mc + t] = RATIOf * (expf(xp - diag - mx) + EPSf);
}

// ---------------------------------------------------------------------------
// k_sum[bh][m] = sum_n kp[bh][n][m]      (grid 96, block 1024)
// ---------------------------------------------------------------------------
__global__ void __launch_bounds__(1024)
ksum_kernel()
{
    const int bh  = blockIdx.x;
    const int m   = threadIdx.x & 255;
    const int grp = threadIdx.x >> 8;             // 0..3
    float s = 0.f;
    for (int n = grp; n < Nc; n += 4)
        s += g_kp[((size_t)bh * Nc + n) * Mc + m];
    __shared__ float sm[1024];
    sm[threadIdx.x] = s;
    __syncthreads();
    if (grp == 0)
        g_ksum[(size_t)bh * Mc + m] = sm[m] + sm[256 + m] + sm[512 + m] + sm[768 + m];
}

// ---------------------------------------------------------------------------
// ctx[bh][m][d] = sum_n kp[bh][n][m] * v[bh][n][d]
// grid (2 m-tiles, 96 heads), block 256, tile 128(m) x 64(d), K-chunk 16(n)
// ---------------------------------------------------------------------------
__global__ void __launch_bounds__(256)
ctx_gemm()
{
    const int bh    = blockIdx.y;
    const int mBase = blockIdx.x * 128;
    __shared__ float As[16][128];
    __shared__ float Bs[16][64];
    const int tid = threadIdx.x;
    const int tx  = tid & 15;
    const int ty  = tid >> 4;

    float acc[8][4];
#pragma unroll
    for (int i = 0; i < 8; i++)
#pragma unroll
        for (int j = 0; j < 4; j++) acc[i][j] = 0.f;

    const float* kp = g_kp + (size_t)bh * Nc * Mc;
    const float* vv = g_v  + (size_t)bh * Nc * DHc;

    for (int n0 = 0; n0 < Nc; n0 += 16) {
        for (int f = tid; f < 512; f += 256) {
            int kk = f >> 5, mq = f & 31;
            *(float4*)&As[kk][mq * 4] =
                *(const float4*)&kp[(size_t)(n0 + kk) * Mc + mBase + mq * 4];
        }
        {
            int kk = tid >> 4, dq = tid & 15;
            *(float4*)&Bs[kk][dq * 4] =
                *(const float4*)&vv[(size_t)(n0 + kk) * DHc + dq * 4];
        }
        __syncthreads();
#pragma unroll
        for (int kk = 0; kk < 16; kk++) {
            float a[8], b[4];
            *(float4*)(a)     = *(const float4*)&As[kk][ty * 8];
            *(float4*)(a + 4) = *(const float4*)&As[kk][ty * 8 + 4];
            *(float4*)(b)     = *(const float4*)&Bs[kk][tx * 4];
#pragma unroll
            for (int i = 0; i < 8; i++)
#pragma unroll
                for (int j = 0; j < 4; j++)
                    acc[i][j] += a[i] * b[j];
        }
        __syncthreads();
    }

    float* dst = g_ctx + (size_t)bh * Mc * DHc;
#pragma unroll
    for (int i = 0; i < 8; i++)
#pragma unroll
        for (int j = 0; j < 4; j++)
            dst[(size_t)(mBase + ty * 8 + i) * DHc + tx * 4 + j] = acc[i][j];
}

// ---------------------------------------------------------------------------
// D_inv[r] = 1 / (qp[r,:] . ksum[bh,:])     one warp per row
// ---------------------------------------------------------------------------
__global__ void __launch_bounds__(256)
dinv_kernel()
{
    const int r    = blockIdx.x * 8 + (threadIdx.x >> 5);
    const int lane = threadIdx.x & 31;
    const int bh   = r >> 11;
    const float* qpr = g_qp   + (size_t)r  * Mc;
    const float* ks  = g_ksum + (size_t)bh * Mc;
    float s = 0.f;
#pragma unroll
    for (int i = lane; i < Mc; i += 32)
        s += qpr[i] * ks[i];
#pragma unroll
    for (int o = 16; o > 0; o >>= 1)
        s += __shfl_xor_sync(0xffffffffu, s, o);
    if (lane == 0) g_dinv[r] = 1.0f / s;
}

// ---------------------------------------------------------------------------
// out[row][d] = dinv[row] * sum_m qp[row][m] * ctx[bh][m][d]
// grid 1536 row-tiles of 128 (each tile within a single head), block 256
// Writes g_attn in [b*N+n][768] layout.
// ---------------------------------------------------------------------------
__global__ void __launch_bounds__(256)
out_gemm()
{
    const int rowBase = blockIdx.x * 128;
    const int bh = rowBase >> 11;
    __shared__ float As[16][128];
    __shared__ float Bs[16][64];
    const int tid = threadIdx.x;
    const int tx  = tid & 15;
    const int ty  = tid >> 4;

    float acc[8][4];
#pragma unroll
    for (int i = 0; i < 8; i++)
#pragma unroll
        for (int j = 0; j < 4; j++) acc[i][j] = 0.f;

    const float* ctx = g_ctx + (size_t)bh * Mc * DHc;

    for (int k0 = 0; k0 < Mc; k0 += 16) {
        for (int f = tid; f < 512; f += 256) {
            int r  = f >> 2;
            int kc = (f & 3) << 2;
            float4 va = *(const float4*)&g_qp[(size_t)(rowBase + r) * Mc + k0 + kc];
            As[kc + 0][r] = va.x; As[kc + 1][r] = va.y;
            As[kc + 2][r] = va.z; As[kc + 3][r] = va.w;
        }
        {
            int kk = tid >> 4, dq = tid & 15;
            *(float4*)&Bs[kk][dq * 4] =
                *(const float4*)&ctx[(size_t)(k0 + kk) * DHc + dq * 4];
        }
        __syncthreads();
#pragma unroll
        for (int kk = 0; kk < 16; kk++) {
            float a[8], b[4];
            *(float4*)(a)     = *(const float4*)&As[kk][ty * 8];
            *(float4*)(a + 4) = *(const float4*)&As[kk][ty * 8 + 4];
            *(float4*)(b)     = *(const float4*)&Bs[kk][tx * 4];
#pragma unroll
            for (int i = 0; i < 8; i++)
#pragma unroll
                for (int j = 0; j < 4; j++)
                    acc[i][j] += a[i] * b[j];
        }
        __syncthreads();
    }

    const int b = bh / Hc;
    const int h = bh % Hc;
#pragma unroll
    for (int i = 0; i < 8; i++) {
        const int row = rowBase + ty * 8 + i;
        const int n   = row & 2047;
        const float sc = g_dinv[row];
#pragma unroll
        for (int j = 0; j < 4; j++)
            g_attn[(size_t)(b * Nc + n) * Dc + h * 64 + tx * 4 + j] = acc[i][j] * sc;
    }
}

// ---------------------------------------------------------------------------
// Launch
// ---------------------------------------------------------------------------
extern "C" void kernel_launch(void* const* d_in, const int* in_sizes, int n_in,
                              void* d_out, int out_size)
{
    const float* x    = (const float*)d_in[0];
    const float* Wq   = (const float*)d_in[1];
    const float* bq   = (const float*)d_in[2];
    const float* Wk   = (const float*)d_in[3];
    const float* bk   = (const float*)d_in[4];
    const float* Wv   = (const float*)d_in[5];
    const float* bv   = (const float*)d_in[6];
    const float* Wo   = (const float*)d_in[7];
    const float* bo   = (const float*)d_in[8];
    const float* proj = (const float*)d_in[9];
    float* out = (float*)d_out;

    float *pq, *pk, *pv, *pqp, *pkp, *pattn;
    cudaGetSymbolAddress((void**)&pq,    g_q);
    cudaGetSymbolAddress((void**)&pk,    g_k);
    cudaGetSymbolAddress((void**)&pv,    g_v);
    cudaGetSymbolAddress((void**)&pqp,   g_qp);
    cudaGetSymbolAddress((void**)&pkp,   g_kp);
    cudaGetSymbolAddress((void**)&pattn, g_attn);

    const dim3 blk(256);

    // 1) QKV projections (head-split layout)
    sgemm_nt<<<dim3(6, 128), blk>>>(x, Wq, bq, pq, Dc, Dc, 1.0f, 1);
    sgemm_nt<<<dim3(6, 128), blk>>>(x, Wk, bk, pk, Dc, Dc, 1.0f, 1);
    sgemm_nt<<<dim3(6, 128), blk>>>(x, Wv, bv, pv, Dc, Dc, 1.0f, 1);

    // 2) random-feature projections: xp = dn * (q @ proj^T)
    sgemm_nt<<<dim3(2, 1536), blk>>>(pq, proj, nullptr, pqp, DHc, Mc, DNf, 0);
    sgemm_nt<<<dim3(2, 1536), blk>>>(pk, proj, nullptr, pkp, DHc, Mc, DNf, 0);

    // 3) per-head max over raw key features (before overwriting g_kp!)
    kmax_stage1<<<dim3(16, 96), 256>>>();
    kmax_stage2<<<1, 128>>>();

    // 4) FAVOR+ finalize (in place)
    finalize_phi<<<BHNc, 256>>>(pq, pqp, 1);
    finalize_phi<<<BHNc, 256>>>(pk, pkp, 0);

    // 5) k_sum, ctx, D_inv, per-head output
    ksum_kernel<<<BHc, 1024>>>();
    ctx_gemm<<<dim3(2, BHc), 256>>>();
    dinv_kernel<<<BHNc / 8, 256>>>();
    out_gemm<<<BHNc / 128, 256>>>();

    // 6) output projection
    sgemm_nt<<<dim3(6, 128), blk>>>(pattn, Wo, bo, out, Dc, Dc, 1.0f, 0);
}

// round 14
// speedup vs baseline: 3.2072x; 3.2072x over previous
#include <cuda_runtime.h>
#include <cuda_bf16.h>
#include <math.h>
#include <stdint.h>

// ---------------------------------------------------------------------------
// Problem constants
// ---------------------------------------------------------------------------
#define Bc   8
#define Nc   2048
#define Dc   768
#define Hc   12
#define DHc  64
#define Mc   256
#define BHc  (Bc * Hc)      // 96
#define BHNc (BHc * Nc)     // 196608
#define BNc  (Bc * Nc)      // 16384

#define DNf    0.3535533905932738f   // 64^-0.25
#define DN2f   0.125f
#define RATIOf 0.0625f
#define EPSf   1e-4f

// ---------------------------------------------------------------------------
// Device scratch (static -> no runtime allocation)
// ---------------------------------------------------------------------------
__device__ float g_q   [(size_t)BHNc * DHc];
__device__ float g_k   [(size_t)BHNc * DHc];
__device__ float g_v   [(size_t)BHNc * DHc];
__device__ float g_qp  [(size_t)BHNc * Mc];
__device__ float g_kp  [(size_t)BHNc * Mc];
__device__ float g_ksum[(size_t)BHc * Mc];
__device__ float g_kpart[(size_t)BHc * 16];
__device__ float g_kmax[(size_t)BHc];
__device__ float g_dinv[(size_t)BHNc];

__device__ __align__(128) __nv_bfloat16 g_xh [(size_t)BNc * Dc],  g_xl [(size_t)BNc * Dc];
__device__ __align__(128) __nv_bfloat16 g_wqh[Dc * Dc], g_wql[Dc * Dc];
__device__ __align__(128) __nv_bfloat16 g_wkh[Dc * Dc], g_wkl[Dc * Dc];
__device__ __align__(128) __nv_bfloat16 g_wvh[Dc * Dc], g_wvl[Dc * Dc];
__device__ __align__(128) __nv_bfloat16 g_woh[Dc * Dc], g_wol[Dc * Dc];
__device__ __align__(128) __nv_bfloat16 g_prh[Mc * DHc], g_prl[Mc * DHc];
__device__ __align__(128) __nv_bfloat16 g_qh [(size_t)BHNc * DHc], g_ql [(size_t)BHNc * DHc];
__device__ __align__(128) __nv_bfloat16 g_kh [(size_t)BHNc * DHc], g_kl [(size_t)BHNc * DHc];
__device__ __align__(128) __nv_bfloat16 g_qph[(size_t)BHNc * Mc],  g_qpl[(size_t)BHNc * Mc];
__device__ __align__(128) __nv_bfloat16 g_kpTh[(size_t)BHNc * Mc], g_kpTl[(size_t)BHNc * Mc]; // [bh][m][n]
__device__ __align__(128) __nv_bfloat16 g_vTh[(size_t)BHNc * DHc], g_vTl[(size_t)BHNc * DHc]; // [bh][d][n]
__device__ __align__(128) __nv_bfloat16 g_cxh[(size_t)BHc * DHc * Mc], g_cxl[(size_t)BHc * DHc * Mc]; // ctxT [bh][d][m]
__device__ __align__(128) __nv_bfloat16 g_ath[(size_t)BNc * Dc], g_atl[(size_t)BNc * Dc];

// ---------------------------------------------------------------------------
// PTX helpers (sm_80+ ISA only: mma.sync / ldmatrix / cp.async)
// ---------------------------------------------------------------------------
__device__ __forceinline__ uint32_t smem_u32(const void* p) {
    uint32_t a;
    asm("{ .reg .u64 t; cvta.to.shared.u64 t, %1; cvt.u32.u64 %0, t; }"
        : "=r"(a) : "l"(p));
    return a;
}

__device__ __forceinline__ void cpa16(uint32_t s, const void* g) {
    asm volatile("cp.async.cg.shared.global [%0], [%1], 16;" :: "r"(s), "l"(g));
}
#define CP_COMMIT() asm volatile("cp.async.commit_group;" ::: "memory")
#define CP_WAIT0()  asm volatile("cp.async.wait_group 0;" ::: "memory")
#define CP_WAIT1()  asm volatile("cp.async.wait_group 1;" ::: "memory")

__device__ __forceinline__ void ldsm4(uint32_t* r, uint32_t addr) {
    asm volatile("ldmatrix.sync.aligned.m8n8.x4.shared.b16 {%0,%1,%2,%3}, [%4];"
                 : "=r"(r[0]), "=r"(r[1]), "=r"(r[2]), "=r"(r[3]) : "r"(addr));
}

__device__ __forceinline__ void mma16816(float* c, const uint32_t* a,
                                         uint32_t b0, uint32_t b1) {
    asm volatile(
        "mma.sync.aligned.m16n8k16.row.col.f32.bf16.bf16.f32 "
        "{%0,%1,%2,%3}, {%4,%5,%6,%7}, {%8,%9}, {%0,%1,%2,%3};"
        : "+f"(c[0]), "+f"(c[1]), "+f"(c[2]), "+f"(c[3])
        : "r"(a[0]), "r"(a[1]), "r"(a[2]), "r"(a[3]), "r"(b0), "r"(b1));
}

// ---------------------------------------------------------------------------
// Split-precision bf16 mma.sync GEMM:  C = alpha*(A @ B^T) + bias (fp32 acc)
//   A = Ah+Al : [rows x K] K-major bf16 pairs
//   B = Bh+Bl : [rows x K] K-major bf16 pairs, batched per head via rowsLog2
//   K multiple of 64. CTA tile 128 x NTILE, 256 threads, 2-stage cp.async.
//   3 MMA passes: hi*hi + hi*lo + lo*hi  (fp32 accumulate)
//   MODE: 0 plain fp32 out [row*Nout+col] (*alpha, +bias)
//         1 QKV head-split fp32 (+bias) and optional bf16 hi/lo
//         2 attention out: *dinv[row], bf16 hi/lo -> [b*Nc+n][768] at h*64+col
//         3 ctx transposed: bf16 hi/lo -> ctxT[(bh*64+col)*256 + m]
// ---------------------------------------------------------------------------
template <int NTILE, int MODE>
__global__ void __launch_bounds__(256)
gemm_mma(const __nv_bfloat16* __restrict__ Ah, const __nv_bfloat16* __restrict__ Al,
         const __nv_bfloat16* __restrict__ Bh, const __nv_bfloat16* __restrict__ Bl,
         int K, int rowsLog2, float alpha,
         const float* __restrict__ bias, const float* __restrict__ dinv,
         float* __restrict__ out32,
         __nv_bfloat16* __restrict__ outHi, __nv_bfloat16* __restrict__ outLo,
         int Nout)
{
    extern __shared__ __align__(128) char smem_raw[];
    const uint32_t smemBase = smem_u32(smem_raw);

    constexpr int OFF_AL = 16384;                   // A: 128 rows x 128B
    constexpr int OFF_BH = 32768;
    constexpr int OFF_BL = 32768 + NTILE * 128;
    constexpr int STAGE  = 32768 + NTILE * 256;

    const int tid  = threadIdx.x;
    const int wid  = tid >> 5;
    const int lane = tid & 31;
    const int rowBase = blockIdx.y * 128;
    const int colBase = blockIdx.x * NTILE;
    const int bhB = rowBase >> rowsLog2;

    const __nv_bfloat16* Bh2 = Bh + (size_t)bhB * NTILE * K;
    const __nv_bfloat16* Bl2 = Bl + (size_t)bhB * NTILE * K;

    // warp tiling: NTILE=128 -> 2x4 warps of 64x32 ; NTILE=64 -> 4x2 of 32x32
    constexpr int MT = (NTILE == 128) ? 4 : 2;
    const int mWarp = (NTILE == 128) ? (wid >> 2) * 64 : (wid >> 1) * 32;
    const int nWarp = (NTILE == 128) ? (wid & 3) * 32 : (wid & 1) * 32;

    // per-lane ldmatrix geometry
    const int l7 = lane & 7, gg = lane >> 3;
    const int aRowOff = l7 + ((gg & 1) << 3);
    const int aBit    = gg >> 1;
    const int bRowOff = l7 + ((gg >> 1) << 3);
    const int bBit    = gg & 1;

    uint32_t aRow[MT]; int aXor[MT];
#pragma unroll
    for (int mt = 0; mt < MT; mt++) {
        const int r = mWarp + mt * 16 + aRowOff;
        aRow[mt] = (uint32_t)(r * 128);
        aXor[mt] = r & 7;
    }
    uint32_t bRow[2]; int bXor[2];
#pragma unroll
    for (int g = 0; g < 2; g++) {
        const int r = nWarp + g * 16 + bRowOff;
        bRow[g] = (uint32_t)(r * 128);
        bXor[g] = r & 7;
    }

    float acc[MT][4][4];
#pragma unroll
    for (int mt = 0; mt < MT; mt++)
#pragma unroll
        for (int nt = 0; nt < 4; nt++)
#pragma unroll
            for (int e = 0; e < 4; e++) acc[mt][nt][e] = 0.f;

    const int nChunks = K >> 6;

    // ---- cp.async stage loader ----
    auto load_stage = [&](int c) {
        const uint32_t sd = smemBase + (uint32_t)((c & 1) * STAGE);
        const int kOff = c << 6;
#pragma unroll
        for (int f = tid; f < 1024; f += 256) {
            const int r = f >> 3, i = f & 7;
            const uint32_t sw = (uint32_t)(r * 128 + ((i ^ (r & 7)) << 4));
            const size_t g = (size_t)(rowBase + r) * K + kOff + i * 8;
            cpa16(sd + sw, Ah + g);
            cpa16(sd + OFF_AL + sw, Al + g);
        }
#pragma unroll
        for (int f = tid; f < NTILE * 8; f += 256) {
            const int r = f >> 3, i = f & 7;
            const uint32_t sw = (uint32_t)(r * 128 + ((i ^ (r & 7)) << 4));
            const size_t g = (size_t)(colBase + r) * K + kOff + i * 8;
            cpa16(sd + OFF_BH + sw, Bh2 + g);
            cpa16(sd + OFF_BL + sw, Bl2 + g);
        }
    };

    load_stage(0);
    CP_COMMIT();

    for (int c = 0; c < nChunks; c++) {
        if (c + 1 < nChunks) { load_stage(c + 1); CP_COMMIT(); CP_WAIT1(); }
        else                 { CP_WAIT0(); }
        __syncthreads();

        const uint32_t sb = smemBase + (uint32_t)((c & 1) * STAGE);
#pragma unroll
        for (int ks = 0; ks < 4; ks++) {
            uint32_t a_h[MT][4], a_l[MT][4];
#pragma unroll
            for (int mt = 0; mt < MT; mt++) {
                const uint32_t ad = sb + aRow[mt]
                    + (uint32_t)((((ks << 1) | aBit) ^ aXor[mt]) << 4);
                ldsm4(a_h[mt], ad);
                ldsm4(a_l[mt], ad + OFF_AL);
            }
            uint32_t b_h[2][4], b_l[2][4];
#pragma unroll
            for (int g = 0; g < 2; g++) {
                const uint32_t bd = sb + OFF_BH + bRow[g]
                    + (uint32_t)((((ks << 1) | bBit) ^ bXor[g]) << 4);
                ldsm4(b_h[g], bd);
                ldsm4(b_l[g], bd + (uint32_t)(NTILE * 128));
            }
#pragma unroll
            for (int mt = 0; mt < MT; mt++)
#pragma unroll
                for (int g = 0; g < 2; g++) {
                    mma16816(acc[mt][2*g],   a_h[mt], b_h[g][0], b_h[g][1]);
                    mma16816(acc[mt][2*g+1], a_h[mt], b_h[g][2], b_h[g][3]);
                    mma16816(acc[mt][2*g],   a_h[mt], b_l[g][0], b_l[g][1]);
                    mma16816(acc[mt][2*g+1], a_h[mt], b_l[g][2], b_l[g][3]);
                    mma16816(acc[mt][2*g],   a_l[mt], b_h[g][0], b_h[g][1]);
                    mma16816(acc[mt][2*g+1], a_l[mt], b_h[g][2], b_h[g][3]);
                }
        }
        __syncthreads();
    }

    // ---- epilogue (fragment layout: c0,c1 at (m, n..n+1), c2,c3 at m+8) ----
    const int lq = lane >> 2;        // row within 8
    const int lr = (lane & 3) * 2;   // col pair

    auto emit = [&](int row, int col, float v) {
        if (MODE == 0) {
            float o = v * alpha;
            if (bias) o += bias[col];
            out32[(size_t)row * Nout + col] = o;
        } else if (MODE == 1) {
            const int bb = row >> 11, n = row & 2047;
            const int h = col >> 6, dd = col & 63;
            const float o = v + bias[col];
            const size_t idx = (((size_t)(bb * Hc + h) * Nc + n) << 6) + dd;
            out32[idx] = o;
            if (outHi) {
                __nv_bfloat16 hv = __float2bfloat16(o);
                outHi[idx] = hv;
                outLo[idx] = __float2bfloat16(o - __bfloat162float(hv));
            }
        } else if (MODE == 2) {
            const int bh2 = row >> 11, n = row & 2047;
            const int b = bh2 / Hc, h = bh2 % Hc;
            const float o = v * dinv[row];
            const size_t idx = ((size_t)(b * Nc + n)) * Dc + h * 64 + col;
            __nv_bfloat16 hv = __float2bfloat16(o);
            outHi[idx] = hv;
            outLo[idx] = __float2bfloat16(o - __bfloat162float(hv));
        } else { // MODE 3: ctxT[(bh*64 + col)*256 + m]
            const int bh3 = row >> rowsLog2;
            const int m = row & ((1 << rowsLog2) - 1);
            const size_t idx = ((size_t)(bh3 * DHc + col)) * Mc + m;
            __nv_bfloat16 hv = __float2bfloat16(v);
            outHi[idx] = hv;
            outLo[idx] = __float2bfloat16(v - __bfloat162float(hv));
        }
    };

#pragma unroll
    for (int mt = 0; mt < MT; mt++)
#pragma unroll
        for (int nt = 0; nt < 4; nt++) {
            const int row = rowBase + mWarp + mt * 16 + lq;
            const int col = colBase + nWarp + nt * 8 + lr;
            emit(row,     col,     acc[mt][nt][0]);
            emit(row,     col + 1, acc[mt][nt][1]);
            emit(row + 8, col,     acc[mt][nt][2]);
            emit(row + 8, col + 1, acc[mt][nt][3]);
        }
}

// ---------------------------------------------------------------------------
// fp32 -> bf16 hi/lo split
// ---------------------------------------------------------------------------
__global__ void __launch_bounds__(256)
split_kernel(const float* __restrict__ src, __nv_bfloat16* __restrict__ h,
             __nv_bfloat16* __restrict__ l, int n)
{
    int i = blockIdx.x * 256 + threadIdx.x;
    if (i < n) {
        float v = src[i];
        __nv_bfloat16 hv = __float2bfloat16(v);
        h[i] = hv;
        l[i] = __float2bfloat16(v - __bfloat162float(hv));
    }
}

// ---------------------------------------------------------------------------
// Batched tiled transpose + split: src [z][R][C] fp32 -> dst [z][C][R] bf16x2
// ---------------------------------------------------------------------------
__global__ void __launch_bounds__(256)
transpose_split(const float* __restrict__ src, __nv_bfloat16* __restrict__ dh,
                __nv_bfloat16* __restrict__ dl, int R, int C)
{
    __shared__ float t[32][33];
    const size_t zb = (size_t)blockIdx.z * R * C;
    const int r0 = blockIdx.y * 32, c0 = blockIdx.x * 32;
    const int tx = threadIdx.x & 31, ty = threadIdx.x >> 5;
#pragma unroll
    for (int i = 0; i < 4; i++)
        t[ty + i * 8][tx] = src[zb + (size_t)(r0 + ty + i * 8) * C + c0 + tx];
    __syncthreads();
#pragma unroll
    for (int i = 0; i < 4; i++) {
        const int cc = c0 + ty + i * 8;
        const int rr = r0 + tx;
        const float v = t[tx][ty + i * 8];
        __nv_bfloat16 hv = __float2bfloat16(v);
        dh[zb + (size_t)cc * R + rr] = hv;
        dl[zb + (size_t)cc * R + rr] = __float2bfloat16(v - __bfloat162float(hv));
    }
}

// ---------------------------------------------------------------------------
// Per-head max of raw key features (two-stage)
// ---------------------------------------------------------------------------
__global__ void kmax_stage1()
{
    const int bh = blockIdx.y, part = blockIdx.x;
    const int chunk = Nc * Mc / 16;
    const size_t base = (size_t)bh * Nc * Mc + (size_t)part * chunk;
    float m = -3.0e38f;
    for (int i = threadIdx.x; i < chunk; i += 256)
        m = fmaxf(m, g_kp[base + i]);
#pragma unroll
    for (int o = 16; o > 0; o >>= 1)
        m = fmaxf(m, __shfl_xor_sync(0xffffffffu, m, o));
    __shared__ float sm[8];
    if ((threadIdx.x & 31) == 0) sm[threadIdx.x >> 5] = m;
    __syncthreads();
    if (threadIdx.x == 0) {
        float mm = sm[0];
#pragma unroll
        for (int i = 1; i < 8; i++) mm = fmaxf(mm, sm[i]);
        g_kpart[bh * 16 + part] = mm;
    }
}

__global__ void kmax_stage2()
{
    const int bh = threadIdx.x;
    if (bh >= BHc) return;
    float m = -3.0e38f;
#pragma unroll
    for (int i = 0; i < 16; i++) m = fmaxf(m, g_kpart[bh * 16 + i]);
    g_kmax[bh] = m;
}

// ---------------------------------------------------------------------------
// FAVOR+ finalize (in place) + optional bf16 hi/lo output
// ---------------------------------------------------------------------------
__global__ void __launch_bounds__(256)
finalize_phi(const float* __restrict__ qk, float* __restrict__ phi, int isQuery,
             __nv_bfloat16* __restrict__ outHi, __nv_bfloat16* __restrict__ outLo)
{
    const int r = blockIdx.x, t = threadIdx.x, bh = r >> 11;
    __shared__ float sA[8], sB[8];

    float xv = (t < DHc) ? qk[(size_t)r * DHc + t] : 0.f;
    float sq = xv * xv;
#pragma unroll
    for (int o = 16; o > 0; o >>= 1)
        sq += __shfl_xor_sync(0xffffffffu, sq, o);
    if ((t & 31) == 0) sA[t >> 5] = sq;

    const float xp = phi[(size_t)r * Mc + t];

    float mx;
    if (isQuery) {
        float m = xp;
#pragma unroll
        for (int o = 16; o > 0; o >>= 1)
            m = fmaxf(m, __shfl_xor_sync(0xffffffffu, m, o));
        if ((t & 31) == 0) sB[t >> 5] = m;
        __syncthreads();
        mx = sB[0];
#pragma unroll
        for (int i = 1; i < 8; i++) mx = fmaxf(mx, sB[i]);
    } else {
        __syncthreads();
        mx = g_kmax[bh];
    }

    float ssum = sA[0];
#pragma unroll
    for (int i = 1; i < 8; i++) ssum += sA[i];
    const float diag = 0.5f * DN2f * ssum;

    const float val = RATIOf * (expf(xp - diag - mx) + EPSf);
    const size_t idx = (size_t)r * Mc + t;
    phi[idx] = val;
    if (outHi) {
        __nv_bfloat16 hv = __float2bfloat16(val);
        outHi[idx] = hv;
        outLo[idx] = __float2bfloat16(val - __bfloat162float(hv));
    }
}

// ---------------------------------------------------------------------------
// k_sum[bh][m] = sum_n kp[bh][n][m]
// ---------------------------------------------------------------------------
__global__ void __launch_bounds__(1024)
ksum_kernel()
{
    const int bh = blockIdx.x;
    const int m = threadIdx.x & 255, grp = threadIdx.x >> 8;
    float s = 0.f;
    for (int n = grp; n < Nc; n += 4)
        s += g_kp[((size_t)bh * Nc + n) * Mc + m];
    __shared__ float sm[1024];
    sm[threadIdx.x] = s;
    __syncthreads();
    if (grp == 0)
        g_ksum[(size_t)bh * Mc + m] = sm[m] + sm[256 + m] + sm[512 + m] + sm[768 + m];
}

// ---------------------------------------------------------------------------
// D_inv[r] = 1 / (qp[r,:] . ksum[bh,:])
// ---------------------------------------------------------------------------
__global__ void __launch_bounds__(256)
dinv_kernel()
{
    const int r = blockIdx.x * 8 + (threadIdx.x >> 5);
    const int lane = threadIdx.x & 31;
    const int bh = r >> 11;
    const float* qpr = g_qp + (size_t)r * Mc;
    const float* ks  = g_ksum + (size_t)bh * Mc;
    float s = 0.f;
#pragma unroll
    for (int i = lane; i < Mc; i += 32)
        s += qpr[i] * ks[i];
#pragma unroll
    for (int o = 16; o > 0; o >>= 1)
        s += __shfl_xor_sync(0xffffffffu, s, o);
    if (lane == 0) g_dinv[r] = 1.0f / s;
}

// ---------------------------------------------------------------------------
// Launch
// ---------------------------------------------------------------------------
extern "C" void kernel_launch(void* const* d_in, const int* in_sizes, int n_in,
                              void* d_out, int out_size)
{
    const float* x    = (const float*)d_in[0];
    const float* Wq   = (const float*)d_in[1];
    const float* bq   = (const float*)d_in[2];
    const float* Wk   = (const float*)d_in[3];
    const float* bk   = (const float*)d_in[4];
    const float* Wv   = (const float*)d_in[5];
    const float* bv   = (const float*)d_in[6];
    const float* Wo   = (const float*)d_in[7];
    const float* bo   = (const float*)d_in[8];
    const float* proj = (const float*)d_in[9];
    float* out = (float*)d_out;

    float *pq, *pk, *pv, *pqp, *pkp, *pdinv;
    __nv_bfloat16 *pxh, *pxl, *pwqh, *pwql, *pwkh, *pwkl, *pwvh, *pwvl,
                  *pwoh, *pwol, *pprh, *pprl, *pqh, *pql, *pkh, *pkl,
                  *pqph, *pqpl, *pkpTh, *pkpTl, *pvTh, *pvTl,
                  *pcxh, *pcxl, *path, *patl;
    cudaGetSymbolAddress((void**)&pq, g_q);       cudaGetSymbolAddress((void**)&pk, g_k);
    cudaGetSymbolAddress((void**)&pv, g_v);       cudaGetSymbolAddress((void**)&pqp, g_qp);
    cudaGetSymbolAddress((void**)&pkp, g_kp);     cudaGetSymbolAddress((void**)&pdinv, g_dinv);
    cudaGetSymbolAddress((void**)&pxh, g_xh);     cudaGetSymbolAddress((void**)&pxl, g_xl);
    cudaGetSymbolAddress((void**)&pwqh, g_wqh);   cudaGetSymbolAddress((void**)&pwql, g_wql);
    cudaGetSymbolAddress((void**)&pwkh, g_wkh);   cudaGetSymbolAddress((void**)&pwkl, g_wkl);
    cudaGetSymbolAddress((void**)&pwvh, g_wvh);   cudaGetSymbolAddress((void**)&pwvl, g_wvl);
    cudaGetSymbolAddress((void**)&pwoh, g_woh);   cudaGetSymbolAddress((void**)&pwol, g_wol);
    cudaGetSymbolAddress((void**)&pprh, g_prh);   cudaGetSymbolAddress((void**)&pprl, g_prl);
    cudaGetSymbolAddress((void**)&pqh, g_qh);     cudaGetSymbolAddress((void**)&pql, g_ql);
    cudaGetSymbolAddress((void**)&pkh, g_kh);     cudaGetSymbolAddress((void**)&pkl, g_kl);
    cudaGetSymbolAddress((void**)&pqph, g_qph);   cudaGetSymbolAddress((void**)&pqpl, g_qpl);
    cudaGetSymbolAddress((void**)&pkpTh, g_kpTh); cudaGetSymbolAddress((void**)&pkpTl, g_kpTl);
    cudaGetSymbolAddress((void**)&pvTh, g_vTh);   cudaGetSymbolAddress((void**)&pvTl, g_vTl);
    cudaGetSymbolAddress((void**)&pcxh, g_cxh);   cudaGetSymbolAddress((void**)&pcxl, g_cxl);
    cudaGetSymbolAddress((void**)&path, g_ath);   cudaGetSymbolAddress((void**)&patl, g_atl);

    const int SM128 = 2 * (32768 + 128 * 256);   // 131072
    const int SM64  = 2 * (32768 + 64 * 256);    //  98304
    cudaFuncSetAttribute(gemm_mma<128, 0>, cudaFuncAttributeMaxDynamicSharedMemorySize, SM128);
    cudaFuncSetAttribute(gemm_mma<128, 1>, cudaFuncAttributeMaxDynamicSharedMemorySize, SM128);
    cudaFuncSetAttribute(gemm_mma<64, 2>,  cudaFuncAttributeMaxDynamicSharedMemorySize, SM64);
    cudaFuncSetAttribute(gemm_mma<64, 3>,  cudaFuncAttributeMaxDynamicSharedMemorySize, SM64);

    // 0) split inputs to bf16 hi/lo
    split_kernel<<<(BNc * Dc + 255) / 256, 256>>>(x, pxh, pxl, BNc * Dc);
    split_kernel<<<(Dc * Dc + 255) / 256, 256>>>(Wq, pwqh, pwql, Dc * Dc);
    split_kernel<<<(Dc * Dc + 255) / 256, 256>>>(Wk, pwkh, pwkl, Dc * Dc);
    split_kernel<<<(Dc * Dc + 255) / 256, 256>>>(Wv, pwvh, pwvl, Dc * Dc);
    split_kernel<<<(Dc * Dc + 255) / 256, 256>>>(Wo, pwoh, pwol, Dc * Dc);
    split_kernel<<<(Mc * DHc + 255) / 256, 256>>>(proj, pprh, pprl, Mc * DHc);

    // 1) QKV projections (head-split epilogue; q/k also write bf16 splits)
    gemm_mma<128, 1><<<dim3(6, 128), 256, SM128>>>(pxh, pxl, pwqh, pwql, Dc, 30, 1.0f,
        bq, nullptr, pq, pqh, pql, Dc);
    gemm_mma<128, 1><<<dim3(6, 128), 256, SM128>>>(pxh, pxl, pwkh, pwkl, Dc, 30, 1.0f,
        bk, nullptr, pk, pkh, pkl, Dc);
    gemm_mma<128, 1><<<dim3(6, 128), 256, SM128>>>(pxh, pxl, pwvh, pwvl, Dc, 30, 1.0f,
        bv, nullptr, pv, nullptr, nullptr, Dc);

    // 2) random-feature projections: xp = dn * (q @ proj^T)
    gemm_mma<128, 0><<<dim3(2, 1536), 256, SM128>>>(pqh, pql, pprh, pprl, DHc, 30, DNf,
        nullptr, nullptr, pqp, nullptr, nullptr, Mc);
    gemm_mma<128, 0><<<dim3(2, 1536), 256, SM128>>>(pkh, pkl, pprh, pprl, DHc, 30, DNf,
        nullptr, nullptr, pkp, nullptr, nullptr, Mc);

    // 3) per-head max over raw key features (before finalize overwrites kp)
    kmax_stage1<<<dim3(16, 96), 256>>>();
    kmax_stage2<<<1, 128>>>();

    // 4) FAVOR+ finalize (qp also emits bf16 splits for the out-GEMM)
    finalize_phi<<<BHNc, 256>>>(pq, pqp, 1, pqph, pqpl);
    finalize_phi<<<BHNc, 256>>>(pk, pkp, 0, nullptr, nullptr);

    // 5) reductions + transposes
    ksum_kernel<<<BHc, 1024>>>();
    transpose_split<<<dim3(Mc / 32, Nc / 32, BHc), 256>>>(pkp, pkpTh, pkpTl, Nc, Mc);
    transpose_split<<<dim3(DHc / 32, Nc / 32, BHc), 256>>>(pv, pvTh, pvTl, Nc, DHc);

    // 6) ctx per head = kpT @ vT^T ; epilogue writes ctxT[d][m] bf16 splits
    gemm_mma<64, 3><<<dim3(1, BHc * 2), 256, SM64>>>(pkpTh, pkpTl, pvTh, pvTl, Nc, 8, 1.0f,
        nullptr, nullptr, nullptr, pcxh, pcxl, DHc);

    // 7) D_inv, then out = dinv * (qp @ ctxT^T), merged-head bf16 splits
    dinv_kernel<<<BHNc / 8, 256>>>();
    gemm_mma<64, 2><<<dim3(1, BHNc / 128), 256, SM64>>>(pqph, pqpl, pcxh, pcxl, Mc, 11, 1.0f,
        nullptr, pdinv, nullptr, path, patl, Dc);

    // 8) final output projection
    gemm_mma<128, 0><<<dim3(6, 128), 256, SM128>>>(path, patl, pwoh, pwol, Dc, 30, 1.0f,
        bo, nullptr, out, nullptr, nullptr, Dc);
}

// round 15
// speedup vs baseline: 3.2586x; 1.0160x over previous
#include <cuda_runtime.h>
#include <cuda_bf16.h>
#include <math.h>
#include <stdint.h>

// ---------------------------------------------------------------------------
// Problem constants
// ---------------------------------------------------------------------------
#define Bc   8
#define Nc   2048
#define Dc   768
#define Hc   12
#define DHc  64
#define Mc   256
#define BHc  (Bc * Hc)      // 96
#define BHNc (BHc * Nc)     // 196608
#define BNc  (Bc * Nc)      // 16384

#define DNf    0.3535533905932738f   // 64^-0.25
#define DN2f   0.125f
#define RATIOf 0.0625f
#define EPSf   1e-4f

// ---------------------------------------------------------------------------
// Device scratch (static -> no runtime allocation)
// ---------------------------------------------------------------------------
__device__ float g_q   [(size_t)BHNc * DHc];
__device__ float g_k   [(size_t)BHNc * DHc];
__device__ float g_v   [(size_t)BHNc * DHc];
__device__ float g_qp  [(size_t)BHNc * Mc];
__device__ float g_kp  [(size_t)BHNc * Mc];
__device__ float g_ksum[(size_t)BHc * Mc];
__device__ float g_kpart[(size_t)BHc * 16];
__device__ float g_kmax[(size_t)BHc];
__device__ float g_dinv[(size_t)BHNc];

__device__ __align__(128) __nv_bfloat16 g_xh [(size_t)BNc * Dc],  g_xl [(size_t)BNc * Dc];
__device__ __align__(128) __nv_bfloat16 g_wqh[Dc * Dc], g_wql[Dc * Dc];
__device__ __align__(128) __nv_bfloat16 g_wkh[Dc * Dc], g_wkl[Dc * Dc];
__device__ __align__(128) __nv_bfloat16 g_wvh[Dc * Dc], g_wvl[Dc * Dc];
__device__ __align__(128) __nv_bfloat16 g_woh[Dc * Dc], g_wol[Dc * Dc];
__device__ __align__(128) __nv_bfloat16 g_prh[Mc * DHc], g_prl[Mc * DHc];
__device__ __align__(128) __nv_bfloat16 g_qh [(size_t)BHNc * DHc], g_ql [(size_t)BHNc * DHc];
__device__ __align__(128) __nv_bfloat16 g_kh [(size_t)BHNc * DHc], g_kl [(size_t)BHNc * DHc];
__device__ __align__(128) __nv_bfloat16 g_qph[(size_t)BHNc * Mc],  g_qpl[(size_t)BHNc * Mc];
__device__ __align__(128) __nv_bfloat16 g_kpTh[(size_t)BHNc * Mc], g_kpTl[(size_t)BHNc * Mc]; // [bh][m][n]
__device__ __align__(128) __nv_bfloat16 g_vTh[(size_t)BHNc * DHc], g_vTl[(size_t)BHNc * DHc]; // [bh][d][n]
__device__ __align__(128) __nv_bfloat16 g_cxh[(size_t)BHc * DHc * Mc], g_cxl[(size_t)BHc * DHc * Mc]; // ctxT [bh][d][m]
__device__ __align__(128) __nv_bfloat16 g_ath[(size_t)BNc * Dc], g_atl[(size_t)BNc * Dc];

// ---------------------------------------------------------------------------
// PTX helpers (sm_80+ ISA only: mma.sync / ldmatrix / cp.async)
// ---------------------------------------------------------------------------
__device__ __forceinline__ uint32_t smem_u32(const void* p) {
    uint32_t a;
    asm("{ .reg .u64 t; cvta.to.shared.u64 t, %1; cvt.u32.u64 %0, t; }"
        : "=r"(a) : "l"(p));
    return a;
}

__device__ __forceinline__ void cpa16(uint32_t s, const void* g) {
    asm volatile("cp.async.cg.shared.global [%0], [%1], 16;" :: "r"(s), "l"(g));
}
#define CP_COMMIT() asm volatile("cp.async.commit_group;" ::: "memory")
#define CP_WAIT0()  asm volatile("cp.async.wait_group 0;" ::: "memory")
#define CP_WAIT1()  asm volatile("cp.async.wait_group 1;" ::: "memory")

__device__ __forceinline__ void ldsm4(uint32_t* r, uint32_t addr) {
    asm volatile("ldmatrix.sync.aligned.m8n8.x4.shared.b16 {%0,%1,%2,%3}, [%4];"
                 : "=r"(r[0]), "=r"(r[1]), "=r"(r[2]), "=r"(r[3]) : "r"(addr));
}

__device__ __forceinline__ void mma16816(float* c, const uint32_t* a,
                                         uint32_t b0, uint32_t b1) {
    asm volatile(
        "mma.sync.aligned.m16n8k16.row.col.f32.bf16.bf16.f32 "
        "{%0,%1,%2,%3}, {%4,%5,%6,%7}, {%8,%9}, {%0,%1,%2,%3};"
        : "+f"(c[0]), "+f"(c[1]), "+f"(c[2]), "+f"(c[3])
        : "r"(a[0]), "r"(a[1]), "r"(a[2]), "r"(a[3]), "r"(b0), "r"(b1));
}

// ---------------------------------------------------------------------------
// Split-precision bf16 mma.sync GEMM:  C = alpha*(A @ B^T) + bias (fp32 acc)
//   A = Ah+Al : [rows x K] K-major bf16 pairs
//   B = Bh+Bl : [rows x K] K-major bf16 pairs, batched per head via rowsLog2
//   K multiple of 64. CTA tile 128 x NTILE, 256 threads, 2-stage cp.async.
//   3 MMA passes: hi*hi + hi*lo + lo*hi  (fp32 accumulate)
//   MODE: 0 plain fp32 out [row*Nout+col] (*alpha, +bias)
//         1 QKV head-split fp32 (+bias) and optional bf16 hi/lo
//         2 attention out: *dinv[row], bf16 hi/lo -> [b*Nc+n][768] at h*64+col
//         3 ctx transposed: bf16 hi/lo -> ctxT[(bh*64+col)*256 + m]
// ---------------------------------------------------------------------------
template <int NTILE, int MODE>
__global__ void __launch_bounds__(256)
gemm_mma(const __nv_bfloat16* __restrict__ Ah, const __nv_bfloat16* __restrict__ Al,
         const __nv_bfloat16* __restrict__ Bh, const __nv_bfloat16* __restrict__ Bl,
         int K, int rowsLog2, float alpha,
         const float* __restrict__ bias, const float* __restrict__ dinv,
         float* __restrict__ out32,
         __nv_bfloat16* __restrict__ outHi, __nv_bfloat16* __restrict__ outLo,
         int Nout)
{
    extern __shared__ __align__(128) char smem_raw[];
    const uint32_t smemBase = smem_u32(smem_raw);

    constexpr int OFF_AL = 16384;                   // A: 128 rows x 128B
    constexpr int OFF_BH = 32768;
    constexpr int OFF_BL = 32768 + NTILE * 128;
    constexpr int STAGE  = 32768 + NTILE * 256;

    const int tid  = threadIdx.x;
    const int wid  = tid >> 5;
    const int lane = tid & 31;
    const int rowBase = blockIdx.y * 128;
    const int colBase = blockIdx.x * NTILE;
    const int bhB = rowBase >> rowsLog2;

    const __nv_bfloat16* Bh2 = Bh + (size_t)bhB * NTILE * K;
    const __nv_bfloat16* Bl2 = Bl + (size_t)bhB * NTILE * K;

    // warp tiling: NTILE=128 -> 2x4 warps of 64x32 ; NTILE=64 -> 4x2 of 32x32
    constexpr int MT = (NTILE == 128) ? 4 : 2;
    const int mWarp = (NTILE == 128) ? (wid >> 2) * 64 : (wid >> 1) * 32;
    const int nWarp = (NTILE == 128) ? (wid & 3) * 32 : (wid & 1) * 32;

    // per-lane ldmatrix geometry
    const int l7 = lane & 7, gg = lane >> 3;
    const int aRowOff = l7 + ((gg & 1) << 3);
    const int aBit    = gg >> 1;
    const int bRowOff = l7 + ((gg >> 1) << 3);
    const int bBit    = gg & 1;

    uint32_t aRow[MT]; int aXor[MT];
#pragma unroll
    for (int mt = 0; mt < MT; mt++) {
        const int r = mWarp + mt * 16 + aRowOff;
        aRow[mt] = (uint32_t)(r * 128);
        aXor[mt] = r & 7;
    }
    uint32_t bRow[2]; int bXor[2];
#pragma unroll
    for (int g = 0; g < 2; g++) {
        const int r = nWarp + g * 16 + bRowOff;
        bRow[g] = (uint32_t)(r * 128);
        bXor[g] = r & 7;
    }

    float acc[MT][4][4];
#pragma unroll
    for (int mt = 0; mt < MT; mt++)
#pragma unroll
        for (int nt = 0; nt < 4; nt++)
#pragma unroll
            for (int e = 0; e < 4; e++) acc[mt][nt][e] = 0.f;

    const int nChunks = K >> 6;

    // ---- cp.async stage loader ----
    auto load_stage = [&](int c) {
        const uint32_t sd = smemBase + (uint32_t)((c & 1) * STAGE);
        const int kOff = c << 6;
#pragma unroll
        for (int f = tid; f < 1024; f += 256) {
            const int r = f >> 3, i = f & 7;
            const uint32_t sw = (uint32_t)(r * 128 + ((i ^ (r & 7)) << 4));
            const size_t g = (size_t)(rowBase + r) * K + kOff + i * 8;
            cpa16(sd + sw, Ah + g);
            cpa16(sd + OFF_AL + sw, Al + g);
        }
#pragma unroll
        for (int f = tid; f < NTILE * 8; f += 256) {
            const int r = f >> 3, i = f & 7;
            const uint32_t sw = (uint32_t)(r * 128 + ((i ^ (r & 7)) << 4));
            const size_t g = (size_t)(colBase + r) * K + kOff + i * 8;
            cpa16(sd + OFF_BH + sw, Bh2 + g);
            cpa16(sd + OFF_BL + sw, Bl2 + g);
        }
    };

    load_stage(0);
    CP_COMMIT();

    for (int c = 0; c < nChunks; c++) {
        if (c + 1 < nChunks) { load_stage(c + 1); CP_COMMIT(); CP_WAIT1(); }
        else                 { CP_WAIT0(); }
        __syncthreads();

        const uint32_t sb = smemBase + (uint32_t)((c & 1) * STAGE);
#pragma unroll
        for (int ks = 0; ks < 4; ks++) {
            uint32_t a_h[MT][4], a_l[MT][4];
#pragma unroll
            for (int mt = 0; mt < MT; mt++) {
                const uint32_t ad = sb + aRow[mt]
                    + (uint32_t)((((ks << 1) | aBit) ^ aXor[mt]) << 4);
                ldsm4(a_h[mt], ad);
                ldsm4(a_l[mt], ad + OFF_AL);
            }
            uint32_t b_h[2][4], b_l[2][4];
#pragma unroll
            for (int g = 0; g < 2; g++) {
                const uint32_t bd = sb + OFF_BH + bRow[g]
                    + (uint32_t)((((ks << 1) | bBit) ^ bXor[g]) << 4);
                ldsm4(b_h[g], bd);
                ldsm4(b_l[g], bd + (uint32_t)(NTILE * 128));
            }
#pragma unroll
            for (int mt = 0; mt < MT; mt++)
#pragma unroll
                for (int g = 0; g < 2; g++) {
                    mma16816(acc[mt][2*g],   a_h[mt], b_h[g][0], b_h[g][1]);
                    mma16816(acc[mt][2*g+1], a_h[mt], b_h[g][2], b_h[g][3]);
                    mma16816(acc[mt][2*g],   a_h[mt], b_l[g][0], b_l[g][1]);
                    mma16816(acc[mt][2*g+1], a_h[mt], b_l[g][2], b_l[g][3]);
                    mma16816(acc[mt][2*g],   a_l[mt], b_h[g][0], b_h[g][1]);
                    mma16816(acc[mt][2*g+1], a_l[mt], b_h[g][2], b_h[g][3]);
                }
        }
        __syncthreads();
    }

    // ---- epilogue (fragment layout: c0,c1 at (m, n..n+1), c2,c3 at m+8) ----
    const int lq = lane >> 2;        // row within 8
    const int lr = (lane & 3) * 2;   // col pair

    auto emit = [&](int row, int col, float v) {
        if (MODE == 0) {
            float o = v * alpha;
            if (bias) o += bias[col];
            out32[(size_t)row * Nout + col] = o;
        } else if (MODE == 1) {
            const int bb = row >> 11, n = row & 2047;
            const int h = col >> 6, dd = col & 63;
            const float o = v + bias[col];
            const size_t idx = (((size_t)(bb * Hc + h) * Nc + n) << 6) + dd;
            out32[idx] = o;
            if (outHi) {
                __nv_bfloat16 hv = __float2bfloat16(o);
                outHi[idx] = hv;
                outLo[idx] = __float2bfloat16(o - __bfloat162float(hv));
            }
        } else if (MODE == 2) {
            const int bh2 = row >> 11, n = row & 2047;
            const int b = bh2 / Hc, h = bh2 % Hc;
            const float o = v * dinv[row];
            const size_t idx = ((size_t)(b * Nc + n)) * Dc + h * 64 + col;
            __nv_bfloat16 hv = __float2bfloat16(o);
            outHi[idx] = hv;
            outLo[idx] = __float2bfloat16(o - __bfloat162float(hv));
        } else { // MODE 3: ctxT[(bh*64 + col)*256 + m]
            const int bh3 = row >> rowsLog2;
            const int m = row & ((1 << rowsLog2) - 1);
            const size_t idx = ((size_t)(bh3 * DHc + col)) * Mc + m;
            __nv_bfloat16 hv = __float2bfloat16(v);
            outHi[idx] = hv;
            outLo[idx] = __float2bfloat16(v - __bfloat162float(hv));
        }
    };

#pragma unroll
    for (int mt = 0; mt < MT; mt++)
#pragma unroll
        for (int nt = 0; nt < 4; nt++) {
            const int row = rowBase + mWarp + mt * 16 + lq;
            const int col = colBase + nWarp + nt * 8 + lr;
            emit(row,     col,     acc[mt][nt][0]);
            emit(row,     col + 1, acc[mt][nt][1]);
            emit(row + 8, col,     acc[mt][nt][2]);
            emit(row + 8, col + 1, acc[mt][nt][3]);
        }
}

// ---------------------------------------------------------------------------
// fp32 -> bf16 hi/lo split
// ---------------------------------------------------------------------------
__global__ void __launch_bounds__(256)
split_kernel(const float* __restrict__ src, __nv_bfloat16* __restrict__ h,
             __nv_bfloat16* __restrict__ l, int n)
{
    int i = blockIdx.x * 256 + threadIdx.x;
    if (i < n) {
        float v = src[i];
        __nv_bfloat16 hv = __float2bfloat16(v);
        h[i] = hv;
        l[i] = __float2bfloat16(v - __bfloat162float(hv));
    }
}

// ---------------------------------------------------------------------------
// Batched tiled transpose + split: src [z][R][C] fp32 -> dst [z][C][R] bf16x2
// ---------------------------------------------------------------------------
__global__ void __launch_bounds__(256)
transpose_split(const float* __restrict__ src, __nv_bfloat16* __restrict__ dh,
                __nv_bfloat16* __restrict__ dl, int R, int C)
{
    __shared__ float t[32][33];
    const size_t zb = (size_t)blockIdx.z * R * C;
    const int r0 = blockIdx.y * 32, c0 = blockIdx.x * 32;
    const int tx = threadIdx.x & 31, ty = threadIdx.x >> 5;
#pragma unroll
    for (int i = 0; i < 4; i++)
        t[ty + i * 8][tx] = src[zb + (size_t)(r0 + ty + i * 8) * C + c0 + tx];
    __syncthreads();
#pragma unroll
    for (int i = 0; i < 4; i++) {
        const int cc = c0 + ty + i * 8;
        const int rr = r0 + tx;
        const float v = t[tx][ty + i * 8];
        __nv_bfloat16 hv = __float2bfloat16(v);
        dh[zb + (size_t)cc * R + rr] = hv;
        dl[zb + (size_t)cc * R + rr] = __float2bfloat16(v - __bfloat162float(hv));
    }
}

// ---------------------------------------------------------------------------
// Per-head max of raw key features (two-stage)
// ---------------------------------------------------------------------------
__global__ void kmax_stage1()
{
    const int bh = blockIdx.y, part = blockIdx.x;
    const int chunk = Nc * Mc / 16;
    const size_t base = (size_t)bh * Nc * Mc + (size_t)part * chunk;
    float m = -3.0e38f;
    for (int i = threadIdx.x; i < chunk; i += 256)
        m = fmaxf(m, g_kp[base + i]);
#pragma unroll
    for (int o = 16; o > 0; o >>= 1)
        m = fmaxf(m, __shfl_xor_sync(0xffffffffu, m, o));
    __shared__ float sm[8];
    if ((threadIdx.x & 31) == 0) sm[threadIdx.x >> 5] = m;
    __syncthreads();
    if (threadIdx.x == 0) {
        float mm = sm[0];
#pragma unroll
        for (int i = 1; i < 8; i++) mm = fmaxf(mm, sm[i]);
        g_kpart[bh * 16 + part] = mm;
    }
}

__global__ void kmax_stage2()
{
    const int bh = threadIdx.x;
    if (bh >= BHc) return;
    float m = -3.0e38f;
#pragma unroll
    for (int i = 0; i < 16; i++) m = fmaxf(m, g_kpart[bh * 16 + i]);
    g_kmax[bh] = m;
}

// ---------------------------------------------------------------------------
// FAVOR+ finalize (in place) + optional bf16 hi/lo output
// ---------------------------------------------------------------------------
__global__ void __launch_bounds__(256)
finalize_phi(const float* __restrict__ qk, float* __restrict__ phi, int isQuery,
             __nv_bfloat16* __restrict__ outHi, __nv_bfloat16* __restrict__ outLo)
{
    const int r = blockIdx.x, t = threadIdx.x, bh = r >> 11;
    __shared__ float sA[8], sB[8];

    float xv = (t < DHc) ? qk[(size_t)r * DHc + t] : 0.f;
    float sq = xv * xv;
#pragma unroll
    for (int o = 16; o > 0; o >>= 1)
        sq += __shfl_xor_sync(0xffffffffu, sq, o);
    if ((t & 31) == 0) sA[t >> 5] = sq;

    const float xp = phi[(size_t)r * Mc + t];

    float mx;
    if (isQuery) {
        float m = xp;
#pragma unroll
        for (int o = 16; o > 0; o >>= 1)
            m = fmaxf(m, __shfl_xor_sync(0xffffffffu, m, o));
        if ((t & 31) == 0) sB[t >> 5] = m;
        __syncthreads();
        mx = sB[0];
#pragma unroll
        for (int i = 1; i < 8; i++) mx = fmaxf(mx, sB[i]);
    } else {
        __syncthreads();
        mx = g_kmax[bh];
    }

    float ssum = sA[0];
#pragma unroll
    for (int i = 1; i < 8; i++) ssum += sA[i];
    const float diag = 0.5f * DN2f * ssum;

    const float val = RATIOf * (expf(xp - diag - mx) + EPSf);
    const size_t idx = (size_t)r * Mc + t;
    phi[idx] = val;
    if (outHi) {
        __nv_bfloat16 hv = __float2bfloat16(val);
        outHi[idx] = hv;
        outLo[idx] = __float2bfloat16(val - __bfloat162float(hv));
    }
}

// ---------------------------------------------------------------------------
// k_sum[bh][m] = sum_n kp[bh][n][m]
// ---------------------------------------------------------------------------
__global__ void __launch_bounds__(1024)
ksum_kernel()
{
    const int bh = blockIdx.x;
    const int m = threadIdx.x & 255, grp = threadIdx.x >> 8;
    float s = 0.f;
    for (int n = grp; n < Nc; n += 4)
        s += g_kp[((size_t)bh * Nc + n) * Mc + m];
    __shared__ float sm[1024];
    sm[threadIdx.x] = s;
    __syncthreads();
    if (grp == 0)
        g_ksum[(size_t)bh * Mc + m] = sm[m] + sm[256 + m] + sm[512 + m] + sm[768 + m];
}

// ---------------------------------------------------------------------------
// D_inv[r] = 1 / (qp[r,:] . ksum[bh,:])
// ---------------------------------------------------------------------------
__global__ void __launch_bounds__(256)
dinv_kernel()
{
    const int r = blockIdx.x * 8 + (threadIdx.x >> 5);
    const int lane = threadIdx.x & 31;
    const int bh = r >> 11;
    const float* qpr = g_qp + (size_t)r * Mc;
    const float* ks  = g_ksum + (size_t)bh * Mc;
    float s = 0.f;
#pragma unroll
    for (int i = lane; i < Mc; i += 32)
        s += qpr[i] * ks[i];
#pragma unroll
    for (int o = 16; o > 0; o >>= 1)
        s += __shfl_xor_sync(0xffffffffu, s, o);
    if (lane == 0) g_dinv[r] = 1.0f / s;
}

// ---------------------------------------------------------------------------
// Launch
// ---------------------------------------------------------------------------
extern "C" void kernel_launch(void* const* d_in, const int* in_sizes, int n_in,
                              void* d_out, int out_size)
{
    const float* x    = (const float*)d_in[0];
    const float* Wq   = (const float*)d_in[1];
    const float* bq   = (const float*)d_in[2];
    const float* Wk   = (const float*)d_in[3];
    const float* bk   = (const float*)d_in[4];
    const float* Wv   = (const float*)d_in[5];
    const float* bv   = (const float*)d_in[6];
    const float* Wo   = (const float*)d_in[7];
    const float* bo   = (const float*)d_in[8];
    const float* proj = (const float*)d_in[9];
    float* out = (float*)d_out;

    float *pq, *pk, *pv, *pqp, *pkp, *pdinv;
    __nv_bfloat16 *pxh, *pxl, *pwqh, *pwql, *pwkh, *pwkl, *pwvh, *pwvl,
                  *pwoh, *pwol, *pprh, *pprl, *pqh, *pql, *pkh, *pkl,
                  *pqph, *pqpl, *pkpTh, *pkpTl, *pvTh, *pvTl,
                  *pcxh, *pcxl, *path, *patl;
    cudaGetSymbolAddress((void**)&pq, g_q);       cudaGetSymbolAddress((void**)&pk, g_k);
    cudaGetSymbolAddress((void**)&pv, g_v);       cudaGetSymbolAddress((void**)&pqp, g_qp);
    cudaGetSymbolAddress((void**)&pkp, g_kp);     cudaGetSymbolAddress((void**)&pdinv, g_dinv);
    cudaGetSymbolAddress((void**)&pxh, g_xh);     cudaGetSymbolAddress((void**)&pxl, g_xl);
    cudaGetSymbolAddress((void**)&pwqh, g_wqh);   cudaGetSymbolAddress((void**)&pwql, g_wql);
    cudaGetSymbolAddress((void**)&pwkh, g_wkh);   cudaGetSymbolAddress((void**)&pwkl, g_wkl);
    cudaGetSymbolAddress((void**)&pwvh, g_wvh);   cudaGetSymbolAddress((void**)&pwvl, g_wvl);
    cudaGetSymbolAddress((void**)&pwoh, g_woh);   cudaGetSymbolAddress((void**)&pwol, g_wol);
    cudaGetSymbolAddress((void**)&pprh, g_prh);   cudaGetSymbolAddress((void**)&pprl, g_prl);
    cudaGetSymbolAddress((void**)&pqh, g_qh);     cudaGetSymbolAddress((void**)&pql, g_ql);
    cudaGetSymbolAddress((void**)&pkh, g_kh);     cudaGetSymbolAddress((void**)&pkl, g_kl);
    cudaGetSymbolAddress((void**)&pqph, g_qph);   cudaGetSymbolAddress((void**)&pqpl, g_qpl);
    cudaGetSymbolAddress((void**)&pkpTh, g_kpTh); cudaGetSymbolAddress((void**)&pkpTl, g_kpTl);
    cudaGetSymbolAddress((void**)&pvTh, g_vTh);   cudaGetSymbolAddress((void**)&pvTl, g_vTl);
    cudaGetSymbolAddress((void**)&pcxh, g_cxh);   cudaGetSymbolAddress((void**)&pcxl, g_cxl);
    cudaGetSymbolAddress((void**)&path, g_ath);   cudaGetSymbolAddress((void**)&patl, g_atl);

    const int SM128 = 2 * (32768 + 128 * 256);   // 131072
    const int SM64  = 2 * (32768 + 64 * 256);    //  98304
    cudaFuncSetAttribute(gemm_mma<128, 0>, cudaFuncAttributeMaxDynamicSharedMemorySize, SM128);
    cudaFuncSetAttribute(gemm_mma<128, 1>, cudaFuncAttributeMaxDynamicSharedMemorySize, SM128);
    cudaFuncSetAttribute(gemm_mma<64, 2>,  cudaFuncAttributeMaxDynamicSharedMemorySize, SM64);
    cudaFuncSetAttribute(gemm_mma<64, 3>,  cudaFuncAttributeMaxDynamicSharedMemorySize, SM64);

    // 0) split inputs to bf16 hi/lo
    split_kernel<<<(BNc * Dc + 255) / 256, 256>>>(x, pxh, pxl, BNc * Dc);
    split_kernel<<<(Dc * Dc + 255) / 256, 256>>>(Wq, pwqh, pwql, Dc * Dc);
    split_kernel<<<(Dc * Dc + 255) / 256, 256>>>(Wk, pwkh, pwkl, Dc * Dc);
    split_kernel<<<(Dc * Dc + 255) / 256, 256>>>(Wv, pwvh, pwvl, Dc * Dc);
    split_kernel<<<(Dc * Dc + 255) / 256, 256>>>(Wo, pwoh, pwol, Dc * Dc);
    split_kernel<<<(Mc * DHc + 255) / 256, 256>>>(proj, pprh, pprl, Mc * DHc);

    // 1) QKV projections (head-split epilogue; q/k also write bf16 splits)
    gemm_mma<128, 1><<<dim3(6, 128), 256, SM128>>>(pxh, pxl, pwqh, pwql, Dc, 30, 1.0f,
        bq, nullptr, pq, pqh, pql, Dc);
    gemm_mma<128, 1><<<dim3(6, 128), 256, SM128>>>(pxh, pxl, pwkh, pwkl, Dc, 30, 1.0f,
        bk, nullptr, pk, pkh, pkl, Dc);
    gemm_mma<128, 1><<<dim3(6, 128), 256, SM128>>>(pxh, pxl, pwvh, pwvl, Dc, 30, 1.0f,
        bv, nullptr, pv, nullptr, nullptr, Dc);

    // 2) random-feature projections: xp = dn * (q @ proj^T)
    gemm_mma<128, 0><<<dim3(2, 1536), 256, SM128>>>(pqh, pql, pprh, pprl, DHc, 30, DNf,
        nullptr, nullptr, pqp, nullptr, nullptr, Mc);
    gemm_mma<128, 0><<<dim3(2, 1536), 256, SM128>>>(pkh, pkl, pprh, pprl, DHc, 30, DNf,
        nullptr, nullptr, pkp, nullptr, nullptr, Mc);

    // 3) per-head max over raw key features (before finalize overwrites kp)
    kmax_stage1<<<dim3(16, 96), 256>>>();
    kmax_stage2<<<1, 128>>>();

    // 4) FAVOR+ finalize (qp also emits bf16 splits for the out-GEMM)
    finalize_phi<<<BHNc, 256>>>(pq, pqp, 1, pqph, pqpl);
    finalize_phi<<<BHNc, 256>>>(pk, pkp, 0, nullptr, nullptr);

    // 5) reductions + transposes
    ksum_kernel<<<BHc, 1024>>>();
    transpose_split<<<dim3(Mc / 32, Nc / 32, BHc), 256>>>(pkp, pkpTh, pkpTl, Nc, Mc);
    transpose_split<<<dim3(DHc / 32, Nc / 32, BHc), 256>>>(pv, pvTh, pvTl, Nc, DHc);

    // 6) ctx per head = kpT @ vT^T ; epilogue writes ctxT[d][m] bf16 splits
    gemm_mma<64, 3><<<dim3(1, BHc * 2), 256, SM64>>>(pkpTh, pkpTl, pvTh, pvTl, Nc, 8, 1.0f,
        nullptr, nullptr, nullptr, pcxh, pcxl, DHc);

    // 7) D_inv, then out = dinv * (qp @ ctxT^T), merged-head bf16 splits
    dinv_kernel<<<BHNc / 8, 256>>>();
    gemm_mma<64, 2><<<dim3(1, BHNc / 128), 256, SM64>>>(pqph, pqpl, pcxh, pcxl, Mc, 11, 1.0f,
        nullptr, pdinv, nullptr, path, patl, Dc);

    // 8) final output projection
    gemm_mma<128, 0><<<dim3(6, 128), 256, SM128>>>(path, patl, pwoh, pwol, Dc, 30, 1.0f,
        bo, nullptr, out, nullptr, nullptr, Dc);
}

// round 16
// speedup vs baseline: 3.7193x; 1.1414x over previous
#include <cuda_runtime.h>
#include <cuda_bf16.h>
#include <math.h>
#include <stdint.h>

// ---------------------------------------------------------------------------
// Problem constants
// ---------------------------------------------------------------------------
#define Bc   8
#define Nc   2048
#define Dc   768
#define Hc   12
#define DHc  64
#define Mc   256
#define BHc  (Bc * Hc)      // 96
#define BHNc (BHc * Nc)     // 196608
#define BNc  (Bc * Nc)      // 16384

#define DNf    0.3535533905932738f   // 64^-0.25
#define DN2f   0.125f
#define RATIOf 0.0625f
#define EPSf   1e-4f

// ---------------------------------------------------------------------------
// Device scratch (static -> no runtime allocation)
// ---------------------------------------------------------------------------
__device__ float g_v    [(size_t)BHNc * DHc];            // fp32 v, head-split
__device__ float g_ksum [(size_t)BHc * Mc];
__device__ float g_kspart[(size_t)BHc * 64 * Mc];        // per-ntile ksum partials
__device__ float g_kpart[1536];                          // per-CTA key max
__device__ float g_kmax [BHc];
__device__ float g_diagk[(size_t)BHNc];
__device__ float g_bcat [3 * Dc];

__device__ __align__(128) __nv_bfloat16 g_xh [(size_t)BNc * Dc],  g_xl [(size_t)BNc * Dc];
__device__ __align__(128) __nv_bfloat16 g_wch[3 * Dc * Dc], g_wcl[3 * Dc * Dc];   // Wq|Wk|Wv
__device__ __align__(128) __nv_bfloat16 g_woh[Dc * Dc], g_wol[Dc * Dc];
__device__ __align__(128) __nv_bfloat16 g_prh[Mc * DHc], g_prl[Mc * DHc];          // dn * proj
__device__ __align__(128) __nv_bfloat16 g_qh [(size_t)BHNc * DHc], g_ql [(size_t)BHNc * DHc];
__device__ __align__(128) __nv_bfloat16 g_kh [(size_t)BHNc * DHc], g_kl [(size_t)BHNc * DHc];
__device__ __align__(128) __nv_bfloat16 g_qph[(size_t)BHNc * Mc],  g_qpl[(size_t)BHNc * Mc]; // xp(K) then qp(Q)
__device__ __align__(128) __nv_bfloat16 g_kpTh[(size_t)BHNc * Mc], g_kpTl[(size_t)BHNc * Mc]; // [bh][m][n]
__device__ __align__(128) __nv_bfloat16 g_vTh[(size_t)BHNc * DHc], g_vTl[(size_t)BHNc * DHc]; // [bh][d][n]
__device__ __align__(128) __nv_bfloat16 g_cxh[(size_t)BHc * DHc * Mc], g_cxl[(size_t)BHc * DHc * Mc];
__device__ __align__(128) __nv_bfloat16 g_ath[(size_t)BNc * Dc], g_atl[(size_t)BNc * Dc];

// ---------------------------------------------------------------------------
// PTX helpers (sm_80+ ISA: mma.sync / ldmatrix / cp.async)
// ---------------------------------------------------------------------------
__device__ __forceinline__ uint32_t smem_u32(const void* p) {
    uint32_t a;
    asm("{ .reg .u64 t; cvta.to.shared.u64 t, %1; cvt.u32.u64 %0, t; }"
        : "=r"(a) : "l"(p));
    return a;
}
__device__ __forceinline__ void cpa16(uint32_t s, const void* g) {
    asm volatile("cp.async.cg.shared.global [%0], [%1], 16;" :: "r"(s), "l"(g));
}
#define CP_COMMIT() asm volatile("cp.async.commit_group;" ::: "memory")
#define CP_WAIT0()  asm volatile("cp.async.wait_group 0;" ::: "memory")
#define CP_WAIT1()  asm volatile("cp.async.wait_group 1;" ::: "memory")

__device__ __forceinline__ void ldsm4(uint32_t* r, uint32_t addr) {
    asm volatile("ldmatrix.sync.aligned.m8n8.x4.shared.b16 {%0,%1,%2,%3}, [%4];"
                 : "=r"(r[0]), "=r"(r[1]), "=r"(r[2]), "=r"(r[3]) : "r"(addr));
}
__device__ __forceinline__ void mma16816(float* c, const uint32_t* a,
                                         uint32_t b0, uint32_t b1) {
    asm volatile(
        "mma.sync.aligned.m16n8k16.row.col.f32.bf16.bf16.f32 "
        "{%0,%1,%2,%3}, {%4,%5,%6,%7}, {%8,%9}, {%0,%1,%2,%3};"
        : "+f"(c[0]), "+f"(c[1]), "+f"(c[2]), "+f"(c[3])
        : "r"(a[0]), "r"(a[1]), "r"(a[2]), "r"(a[3]), "r"(b0), "r"(b1));
}
__device__ __forceinline__ void bfsplit(float v, __nv_bfloat16& h, __nv_bfloat16& l) {
    h = __float2bfloat16(v);
    l = __float2bfloat16(v - __bfloat162float(h));
}

// ---------------------------------------------------------------------------
// Split-precision bf16 mma.sync GEMM:  C = A @ B^T (+bias), fp32 acc, 3 passes
//   MODE 0: plain fp32 out [row*Nout+col] + bias       (final projection)
//   MODE 1: QKV-cat: col selects Wq/Wk/Wv; head-split; q/k -> bf16 splits, v -> fp32
//   MODE 2: attention out: bf16 hi/lo -> [b*Nc+n][768] at h*64+col
//   MODE 3: ctx transposed: bf16 hi/lo -> ctxT[(bh*64+col)*256 + m]
// ---------------------------------------------------------------------------
template <int NTILE, int MODE>
__global__ void __launch_bounds__(256)
gemm_mma(const __nv_bfloat16* __restrict__ Ah, const __nv_bfloat16* __restrict__ Al,
         const __nv_bfloat16* __restrict__ Bh, const __nv_bfloat16* __restrict__ Bl,
         int K, int rowsLog2,
         const float* __restrict__ bias,
         float* __restrict__ out32,
         __nv_bfloat16* __restrict__ outHi, __nv_bfloat16* __restrict__ outLo,
         int Nout)
{
    extern __shared__ __align__(128) char smem_raw[];
    const uint32_t smemBase = smem_u32(smem_raw);

    constexpr int OFF_AL = 16384;
    constexpr int OFF_BH = 32768;
    constexpr int OFF_BL = 32768 + NTILE * 128;
    constexpr int STAGE  = 32768 + NTILE * 256;

    const int tid  = threadIdx.x;
    const int wid  = tid >> 5;
    const int lane = tid & 31;
    const int rowBase = blockIdx.y * 128;
    const int colBase = blockIdx.x * NTILE;
    const int bhB = rowBase >> rowsLog2;

    const __nv_bfloat16* Bh2 = Bh + (size_t)bhB * NTILE * K;
    const __nv_bfloat16* Bl2 = Bl + (size_t)bhB * NTILE * K;

    constexpr int MT = (NTILE == 128) ? 4 : 2;
    const int mWarp = (NTILE == 128) ? (wid >> 2) * 64 : (wid >> 1) * 32;
    const int nWarp = (NTILE == 128) ? (wid & 3) * 32 : (wid & 1) * 32;

    const int l7 = lane & 7, gg = lane >> 3;
    const int aRowOff = l7 + ((gg & 1) << 3);
    const int aBit    = gg >> 1;
    const int bRowOff = l7 + ((gg >> 1) << 3);
    const int bBit    = gg & 1;

    uint32_t aRow[MT]; int aXor[MT];
#pragma unroll
    for (int mt = 0; mt < MT; mt++) {
        const int r = mWarp + mt * 16 + aRowOff;
        aRow[mt] = (uint32_t)(r * 128);
        aXor[mt] = r & 7;
    }
    uint32_t bRow[2]; int bXor[2];
#pragma unroll
    for (int g = 0; g < 2; g++) {
        const int r = nWarp + g * 16 + bRowOff;
        bRow[g] = (uint32_t)(r * 128);
        bXor[g] = r & 7;
    }

    float acc[MT][4][4];
#pragma unroll
    for (int mt = 0; mt < MT; mt++)
#pragma unroll
        for (int nt = 0; nt < 4; nt++)
#pragma unroll
            for (int e = 0; e < 4; e++) acc[mt][nt][e] = 0.f;

    const int nChunks = K >> 6;

    auto load_stage = [&](int c) {
        const uint32_t sd = smemBase + (uint32_t)((c & 1) * STAGE);
        const int kOff = c << 6;
#pragma unroll
        for (int f = tid; f < 1024; f += 256) {
            const int r = f >> 3, i = f & 7;
            const uint32_t sw = (uint32_t)(r * 128 + ((i ^ (r & 7)) << 4));
            const size_t g = (size_t)(rowBase + r) * K + kOff + i * 8;
            cpa16(sd + sw, Ah + g);
            cpa16(sd + OFF_AL + sw, Al + g);
        }
#pragma unroll
        for (int f = tid; f < NTILE * 8; f += 256) {
            const int r = f >> 3, i = f & 7;
            const uint32_t sw = (uint32_t)(r * 128 + ((i ^ (r & 7)) << 4));
            const size_t g = (size_t)(colBase + r) * K + kOff + i * 8;
            cpa16(sd + OFF_BH + sw, Bh2 + g);
            cpa16(sd + OFF_BL + sw, Bl2 + g);
        }
    };

    load_stage(0);
    CP_COMMIT();

    for (int c = 0; c < nChunks; c++) {
        if (c + 1 < nChunks) { load_stage(c + 1); CP_COMMIT(); CP_WAIT1(); }
        else                 { CP_WAIT0(); }
        __syncthreads();

        const uint32_t sb = smemBase + (uint32_t)((c & 1) * STAGE);
#pragma unroll
        for (int ks = 0; ks < 4; ks++) {
            uint32_t a_h[MT][4], a_l[MT][4];
#pragma unroll
            for (int mt = 0; mt < MT; mt++) {
                const uint32_t ad = sb + aRow[mt]
                    + (uint32_t)((((ks << 1) | aBit) ^ aXor[mt]) << 4);
                ldsm4(a_h[mt], ad);
                ldsm4(a_l[mt], ad + OFF_AL);
            }
            uint32_t b_h[2][4], b_l[2][4];
#pragma unroll
            for (int g = 0; g < 2; g++) {
                const uint32_t bd = sb + OFF_BH + bRow[g]
                    + (uint32_t)((((ks << 1) | bBit) ^ bXor[g]) << 4);
                ldsm4(b_h[g], bd);
                ldsm4(b_l[g], bd + (uint32_t)(NTILE * 128));
            }
#pragma unroll
            for (int mt = 0; mt < MT; mt++)
#pragma unroll
                for (int g = 0; g < 2; g++) {
                    mma16816(acc[mt][2*g],   a_h[mt], b_h[g][0], b_h[g][1]);
                    mma16816(acc[mt][2*g+1], a_h[mt], b_h[g][2], b_h[g][3]);
                    mma16816(acc[mt][2*g],   a_h[mt], b_l[g][0], b_l[g][1]);
                    mma16816(acc[mt][2*g+1], a_h[mt], b_l[g][2], b_l[g][3]);
                    mma16816(acc[mt][2*g],   a_l[mt], b_h[g][0], b_h[g][1]);
                    mma16816(acc[mt][2*g+1], a_l[mt], b_h[g][2], b_h[g][3]);
                }
        }
        __syncthreads();
    }

    const int lq = lane >> 2;
    const int lr = (lane & 3) * 2;

    auto emit = [&](int row, int col, float v) {
        if (MODE == 0) {
            out32[(size_t)row * Nout + col] = v + bias[col];
        } else if (MODE == 1) {
            const int mat = col / Dc;
            const int c = col - mat * Dc;
            const int h = c >> 6, dd = c & 63;
            const int bb = row >> 11, n = row & 2047;
            const float o = v + bias[col];
            const size_t idx = (((size_t)(bb * Hc + h) * Nc + n) << 6) + dd;
            if (mat == 0)      bfsplit(o, g_qh[idx], g_ql[idx]);
            else if (mat == 1) bfsplit(o, g_kh[idx], g_kl[idx]);
            else               g_v[idx] = o;
        } else if (MODE == 2) {
            const int bh2 = row >> 11, n = row & 2047;
            const int b = bh2 / Hc, h = bh2 % Hc;
            const size_t idx = ((size_t)(b * Nc + n)) * Dc + h * 64 + col;
            bfsplit(v, outHi[idx], outLo[idx]);
        } else { // MODE 3
            const int bh3 = row >> rowsLog2;
            const int m = row & ((1 << rowsLog2) - 1);
            const size_t idx = ((size_t)(bh3 * DHc + col)) * Mc + m;
            bfsplit(v, outHi[idx], outLo[idx]);
        }
    };

#pragma unroll
    for (int mt = 0; mt < MT; mt++)
#pragma unroll
        for (int nt = 0; nt < 4; nt++) {
            const int row = rowBase + mWarp + mt * 16 + lq;
            const int col = colBase + nWarp + nt * 8 + lr;
            emit(row,     col,     acc[mt][nt][0]);
            emit(row,     col + 1, acc[mt][nt][1]);
            emit(row + 8, col,     acc[mt][nt][2]);
            emit(row + 8, col + 1, acc[mt][nt][3]);
        }
}

// ---------------------------------------------------------------------------
// Fused FAVOR+ feature GEMM: xp = (q|k splits) @ (dn*proj splits)^T
//   tile 128 x 256 (full feature row per CTA), K = 64, 512 threads, 16 warps
//   QUERY: row-max, diag (from A smem), exp, dinv = 1/(qp.ksum), qp *= dinv,
//          write bf16 hi/lo only.
//   KEY:   write raw xp bf16 hi/lo, per-CTA max -> g_kpart, diag -> g_diagk.
// ---------------------------------------------------------------------------
template <int IS_QUERY>
__global__ void __launch_bounds__(512)
feature_gemm(const __nv_bfloat16* __restrict__ Ah, const __nv_bfloat16* __restrict__ Al,
             __nv_bfloat16* __restrict__ outHi, __nv_bfloat16* __restrict__ outLo)
{
    extern __shared__ __align__(128) char smem_raw[];
    const uint32_t sb = smem_u32(smem_raw);
    __shared__ float sred[4][128];
    __shared__ float sdiag[128];
    __shared__ float smax[16];

    const int tid  = threadIdx.x;
    const int wid  = tid >> 5;
    const int lane = tid & 31;
    const int rowBase = blockIdx.x * 128;
    const int bh = rowBase >> 11;

    const int mWarp = (wid >> 2) * 32;
    const int warpN = wid & 3;
    const int nWarp = warpN * 64;

    // ---- load tiles (single K chunk of 64) ----
#pragma unroll
    for (int f = tid; f < 1024; f += 512) {
        const int r = f >> 3, i = f & 7;
        const uint32_t sw = (uint32_t)(r * 128 + ((i ^ (r & 7)) << 4));
        const size_t g = (size_t)(rowBase + r) * DHc + i * 8;
        cpa16(sb + sw, Ah + g);
        cpa16(sb + 16384 + sw, Al + g);
    }
#pragma unroll
    for (int f = tid; f < 2048; f += 512) {
        const int r = f >> 3, i = f & 7;
        const uint32_t sw = (uint32_t)(r * 128 + ((i ^ (r & 7)) << 4));
        const size_t g = (size_t)r * DHc + i * 8;
        cpa16(sb + 32768 + sw, g_prh + g);
        cpa16(sb + 65536 + sw, g_prl + g);
    }
    CP_COMMIT(); CP_WAIT0();
    __syncthreads();

    // ---- MMA ----
    const int l7 = lane & 7, gg = lane >> 3;
    const int aRowOff = l7 + ((gg & 1) << 3);
    const int aBit    = gg >> 1;
    const int bRowOff = l7 + ((gg >> 1) << 3);
    const int bBit    = gg & 1;

    float acc[2][8][4];
#pragma unroll
    for (int mt = 0; mt < 2; mt++)
#pragma unroll
        for (int nt = 0; nt < 8; nt++)
#pragma unroll
            for (int e = 0; e < 4; e++) acc[mt][nt][e] = 0.f;

#pragma unroll
    for (int ks = 0; ks < 4; ks++) {
        uint32_t a_h[2][4], a_l[2][4];
#pragma unroll
        for (int mt = 0; mt < 2; mt++) {
            const int ar = mWarp + mt * 16 + aRowOff;
            const uint32_t ad = sb + (uint32_t)(ar * 128)
                + (uint32_t)((((ks << 1) | aBit) ^ (ar & 7)) << 4);
            ldsm4(a_h[mt], ad);
            ldsm4(a_l[mt], ad + 16384);
        }
#pragma unroll
        for (int g = 0; g < 4; g++) {
            const int br = nWarp + g * 16 + bRowOff;
            const uint32_t bd = sb + 32768 + (uint32_t)(br * 128)
                + (uint32_t)((((ks << 1) | bBit) ^ (br & 7)) << 4);
            uint32_t b_h[4], b_l[4];
            ldsm4(b_h, bd);
            ldsm4(b_l, bd + 32768);
#pragma unroll
            for (int mt = 0; mt < 2; mt++) {
                mma16816(acc[mt][2*g],   a_h[mt], b_h[0], b_h[1]);
                mma16816(acc[mt][2*g+1], a_h[mt], b_h[2], b_h[3]);
                mma16816(acc[mt][2*g],   a_h[mt], b_l[0], b_l[1]);
                mma16816(acc[mt][2*g+1], a_h[mt], b_l[2], b_l[3]);
                mma16816(acc[mt][2*g],   a_l[mt], b_h[0], b_h[1]);
                mma16816(acc[mt][2*g+1], a_l[mt], b_h[2], b_h[3]);
            }
        }
    }

    // ---- diag = 0.5*dn^2*||row||^2 from A smem (hi+lo) ----
    {
        const int r = tid >> 2, p = tid & 3;
        float s = 0.f;
#pragma unroll
        for (int e = 0; e < 16; e++) {
            const int k = p * 16 + e;
            const uint32_t off = (uint32_t)(r * 128 + (((k >> 3) ^ (r & 7)) << 4) + (k & 7) * 2);
            const float hv = __bfloat162float(*(const __nv_bfloat16*)(smem_raw + off));
            const float lv = __bfloat162float(*(const __nv_bfloat16*)(smem_raw + 16384 + off));
            const float v = hv + lv;
            s += v * v;
        }
        s += __shfl_xor_sync(0xffffffffu, s, 1);
        s += __shfl_xor_sync(0xffffffffu, s, 2);
        if (p == 0) sdiag[r] = 0.5f * DN2f * s;
    }
    __syncthreads();

    const int lq = lane >> 2;
    const int lr = (lane & 3) * 2;
    const int rowLoc0 = mWarp + lq;

    if (IS_QUERY) {
        // ---- row max (strip -> cross-warp) ----
        float m_[2][2];
#pragma unroll
        for (int mt = 0; mt < 2; mt++) {
            float m0 = -3.0e38f, m1 = -3.0e38f;
#pragma unroll
            for (int nt = 0; nt < 8; nt++) {
                m0 = fmaxf(m0, fmaxf(acc[mt][nt][0], acc[mt][nt][1]));
                m1 = fmaxf(m1, fmaxf(acc[mt][nt][2], acc[mt][nt][3]));
            }
            m_[mt][0] = m0; m_[mt][1] = m1;
        }
#pragma unroll
        for (int mt = 0; mt < 2; mt++)
#pragma unroll
            for (int hf = 0; hf < 2; hf++) {
                m_[mt][hf] = fmaxf(m_[mt][hf], __shfl_xor_sync(0xffffffffu, m_[mt][hf], 1));
                m_[mt][hf] = fmaxf(m_[mt][hf], __shfl_xor_sync(0xffffffffu, m_[mt][hf], 2));
            }
        if ((lane & 3) == 0) {
#pragma unroll
            for (int mt = 0; mt < 2; mt++) {
                sred[warpN][rowLoc0 + mt * 16]     = m_[mt][0];
                sred[warpN][rowLoc0 + mt * 16 + 8] = m_[mt][1];
            }
        }
        __syncthreads();
        float mx[2][2], dgv[2][2];
#pragma unroll
        for (int mt = 0; mt < 2; mt++)
#pragma unroll
            for (int hf = 0; hf < 2; hf++) {
                const int row = rowLoc0 + mt * 16 + hf * 8;
                mx[mt][hf] = fmaxf(fmaxf(sred[0][row], sred[1][row]),
                                   fmaxf(sred[2][row], sred[3][row]));
                dgv[mt][hf] = sdiag[row];
            }
        __syncthreads();

        // ---- exp + dot with ksum ----
        float dot[2][2] = {{0.f, 0.f}, {0.f, 0.f}};
#pragma unroll
        for (int mt = 0; mt < 2; mt++)
#pragma unroll
            for (int nt = 0; nt < 8; nt++) {
                const int col = nWarp + nt * 8 + lr;
                const float k0 = g_ksum[bh * Mc + col];
                const float k1 = g_ksum[bh * Mc + col + 1];
#pragma unroll
                for (int e = 0; e < 4; e++) {
                    const int hf = e >> 1;
                    const float v = RATIOf *
                        (expf(acc[mt][nt][e] - dgv[mt][hf] - mx[mt][hf]) + EPSf);
                    acc[mt][nt][e] = v;
                    dot[mt][hf] += v * ((e & 1) ? k1 : k0);
                }
            }
#pragma unroll
        for (int mt = 0; mt < 2; mt++)
#pragma unroll
            for (int hf = 0; hf < 2; hf++) {
                dot[mt][hf] += __shfl_xor_sync(0xffffffffu, dot[mt][hf], 1);
                dot[mt][hf] += __shfl_xor_sync(0xffffffffu, dot[mt][hf], 2);
            }
        if ((lane & 3) == 0) {
#pragma unroll
            for (int mt = 0; mt < 2; mt++) {
                sred[warpN][rowLoc0 + mt * 16]     = dot[mt][0];
                sred[warpN][rowLoc0 + mt * 16 + 8] = dot[mt][1];
            }
        }
        __syncthreads();
#pragma unroll
        for (int mt = 0; mt < 2; mt++)
#pragma unroll
            for (int hf = 0; hf < 2; hf++) {
                const int row = rowLoc0 + mt * 16 + hf * 8;
                const float dv = 1.0f / (sred[0][row] + sred[1][row]
                                       + sred[2][row] + sred[3][row]);
#pragma unroll
                for (int nt = 0; nt < 8; nt++) {
                    acc[mt][nt][2*hf]   *= dv;
                    acc[mt][nt][2*hf+1] *= dv;
                }
            }
    } else {
        // ---- per-CTA max of raw xp ----
        float bm = -3.0e38f;
#pragma unroll
        for (int mt = 0; mt < 2; mt++)
#pragma unroll
            for (int nt = 0; nt < 8; nt++)
#pragma unroll
                for (int e = 0; e < 4; e++) bm = fmaxf(bm, acc[mt][nt][e]);
#pragma unroll
        for (int o = 16; o > 0; o >>= 1)
            bm = fmaxf(bm, __shfl_xor_sync(0xffffffffu, bm, o));
        if (lane == 0) smax[wid] = bm;
        __syncthreads();
        if (tid == 0) {
            float mm = smax[0];
#pragma unroll
            for (int i = 1; i < 16; i++) mm = fmaxf(mm, smax[i]);
            g_kpart[blockIdx.x] = mm;
        }
        if (tid < 128) g_diagk[rowBase + tid] = sdiag[tid];
    }

    // ---- write hi/lo ----
#pragma unroll
    for (int mt = 0; mt < 2; mt++)
#pragma unroll
        for (int nt = 0; nt < 8; nt++)
#pragma unroll
            for (int e = 0; e < 4; e++) {
                const int row = rowBase + rowLoc0 + mt * 16 + (e >> 1) * 8;
                const int col = nWarp + nt * 8 + lr + (e & 1);
                const size_t idx = (size_t)row * Mc + col;
                bfsplit(acc[mt][nt][e], outHi[idx], outLo[idx]);
            }
}

// ---------------------------------------------------------------------------
// key max reduce: 16 per-CTA maxima per head -> g_kmax
// ---------------------------------------------------------------------------
__global__ void kmax_reduce()
{
    const int bh = blockIdx.x, lane = threadIdx.x;
    float v = (lane < 16) ? g_kpart[bh * 16 + lane] : -3.0e38f;
#pragma unroll
    for (int o = 16; o > 0; o >>= 1)
        v = fmaxf(v, __shfl_xor_sync(0xffffffffu, v, o));
    if (lane == 0) g_kmax[bh] = v;
}

// ---------------------------------------------------------------------------
// Fused key finalize + transpose + ksum partials.
// reads xp hi/lo [bh][n][m], writes kpT hi/lo [bh][m][n] + partials
// grid (Mc/32, Nc/32, BHc), block 256
// ---------------------------------------------------------------------------
__global__ void __launch_bounds__(256)
kfin_transpose(const __nv_bfloat16* __restrict__ xph,
               const __nv_bfloat16* __restrict__ xpl)
{
    __shared__ float t[32][33];
    const int bh = blockIdx.z;
    const size_t zb = (size_t)bh * Nc * Mc;
    const int r0 = blockIdx.y * 32, c0 = blockIdx.x * 32;
    const int tx = threadIdx.x & 31, ty = threadIdx.x >> 5;

#pragma unroll
    for (int i = 0; i < 4; i++) {
        const size_t idx = zb + (size_t)(r0 + ty + i * 8) * Mc + c0 + tx;
        t[ty + i * 8][tx] = __bfloat162float(xph[idx]) + __bfloat162float(xpl[idx]);
    }
    __syncthreads();

    const float km = g_kmax[bh];
#pragma unroll
    for (int i = 0; i < 4; i++) {
        const int cc = c0 + ty + i * 8;      // feature m
        const int rr = r0 + tx;              // position n
        const float dg = g_diagk[(size_t)bh * Nc + rr];
        const float v = RATIOf * (expf(t[tx][ty + i * 8] - dg - km) + EPSf);
        const size_t idx = zb + (size_t)cc * Nc + rr;
        bfsplit(v, g_kpTh[idx], g_kpTl[idx]);
        // ksum partial over the 32 n in this tile
        float s = v;
#pragma unroll
        for (int o = 16; o > 0; o >>= 1)
            s += __shfl_xor_sync(0xffffffffu, s, o);
        if (tx == 0)
            g_kspart[((size_t)bh * 64 + blockIdx.y) * Mc + cc] = s;
    }
}

// ---------------------------------------------------------------------------
// ksum partial reduce: sum 64 n-tiles per (bh, m)
// ---------------------------------------------------------------------------
__global__ void __launch_bounds__(256)
ksum_reduce()
{
    const int bh = blockIdx.x, m = threadIdx.x;
    float s = 0.f;
#pragma unroll 8
    for (int i = 0; i < 64; i++)
        s += g_kspart[((size_t)bh * 64 + i) * Mc + m];
    g_ksum[bh * Mc + m] = s;
}

// ---------------------------------------------------------------------------
// fp32 -> bf16 hi/lo split (with optional pre-scale)
// ---------------------------------------------------------------------------
__global__ void __launch_bounds__(256)
split_kernel(const float* __restrict__ src, __nv_bfloat16* __restrict__ h,
             __nv_bfloat16* __restrict__ l, int n, float scale)
{
    int i = blockIdx.x * 256 + threadIdx.x;
    if (i < n) bfsplit(src[i] * scale, h[i], l[i]);
}

__global__ void bias_cat(const float* bq, const float* bk, const float* bv)
{
    const int i = threadIdx.x;
    g_bcat[i] = bq[i];
    g_bcat[Dc + i] = bk[i];
    g_bcat[2 * Dc + i] = bv[i];
}

// ---------------------------------------------------------------------------
// Batched tiled transpose + split for v: [bh][n][64] fp32 -> [bh][64][n] bf16x2
// ---------------------------------------------------------------------------
__global__ void __launch_bounds__(256)
transpose_split(const float* __restrict__ src, __nv_bfloat16* __restrict__ dh,
                __nv_bfloat16* __restrict__ dl, int R, int C)
{
    __shared__ float t[32][33];
    const size_t zb = (size_t)blockIdx.z * R * C;
    const int r0 = blockIdx.y * 32, c0 = blockIdx.x * 32;
    const int tx = threadIdx.x & 31, ty = threadIdx.x >> 5;
#pragma unroll
    for (int i = 0; i < 4; i++)
        t[ty + i * 8][tx] = src[zb + (size_t)(r0 + ty + i * 8) * C + c0 + tx];
    __syncthreads();
#pragma unroll
    for (int i = 0; i < 4; i++) {
        const int cc = c0 + ty + i * 8;
        const int rr = r0 + tx;
        const size_t idx = zb + (size_t)cc * R + rr;
        bfsplit(t[tx][ty + i * 8], dh[idx], dl[idx]);
    }
}

// ---------------------------------------------------------------------------
// Launch
// ---------------------------------------------------------------------------
extern "C" void kernel_launch(void* const* d_in, const int* in_sizes, int n_in,
                              void* d_out, int out_size)
{
    const float* x    = (const float*)d_in[0];
    const float* Wq   = (const float*)d_in[1];
    const float* bq   = (const float*)d_in[2];
    const float* Wk   = (const float*)d_in[3];
    const float* bk   = (const float*)d_in[4];
    const float* Wv   = (const float*)d_in[5];
    const float* bv   = (const float*)d_in[6];
    const float* Wo   = (const float*)d_in[7];
    const float* bo   = (const float*)d_in[8];
    const float* proj = (const float*)d_in[9];
    float* out = (float*)d_out;

    float *pv, *pbcat;
    __nv_bfloat16 *pxh, *pxl, *pwch, *pwcl, *pwoh, *pwol, *pprh, *pprl,
                  *pqh, *pql, *pkh, *pkl, *pqph, *pqpl,
                  *pkpTh, *pkpTl, *pvTh, *pvTl, *pcxh, *pcxl, *path, *patl;
    cudaGetSymbolAddress((void**)&pv, g_v);
    cudaGetSymbolAddress((void**)&pbcat, g_bcat);
    cudaGetSymbolAddress((void**)&pxh, g_xh);     cudaGetSymbolAddress((void**)&pxl, g_xl);
    cudaGetSymbolAddress((void**)&pwch, g_wch);   cudaGetSymbolAddress((void**)&pwcl, g_wcl);
    cudaGetSymbolAddress((void**)&pwoh, g_woh);   cudaGetSymbolAddress((void**)&pwol, g_wol);
    cudaGetSymbolAddress((void**)&pprh, g_prh);   cudaGetSymbolAddress((void**)&pprl, g_prl);
    cudaGetSymbolAddress((void**)&pqh, g_qh);     cudaGetSymbolAddress((void**)&pql, g_ql);
    cudaGetSymbolAddress((void**)&pkh, g_kh);     cudaGetSymbolAddress((void**)&pkl, g_kl);
    cudaGetSymbolAddress((void**)&pqph, g_qph);   cudaGetSymbolAddress((void**)&pqpl, g_qpl);
    cudaGetSymbolAddress((void**)&pkpTh, g_kpTh); cudaGetSymbolAddress((void**)&pkpTl, g_kpTl);
    cudaGetSymbolAddress((void**)&pvTh, g_vTh);   cudaGetSymbolAddress((void**)&pvTl, g_vTl);
    cudaGetSymbolAddress((void**)&pcxh, g_cxh);   cudaGetSymbolAddress((void**)&pcxl, g_cxl);
    cudaGetSymbolAddress((void**)&path, g_ath);   cudaGetSymbolAddress((void**)&patl, g_atl);

    const int SM128 = 2 * (32768 + 128 * 256);   // 131072
    const int SM64  = 2 * (32768 + 64 * 256);    //  98304
    const int SMFEAT = 98304;
    cudaFuncSetAttribute(gemm_mma<128, 0>, cudaFuncAttributeMaxDynamicSharedMemorySize, SM128);
    cudaFuncSetAttribute(gemm_mma<128, 1>, cudaFuncAttributeMaxDynamicSharedMemorySize, SM128);
    cudaFuncSetAttribute(gemm_mma<64, 2>,  cudaFuncAttributeMaxDynamicSharedMemorySize, SM64);
    cudaFuncSetAttribute(gemm_mma<64, 3>,  cudaFuncAttributeMaxDynamicSharedMemorySize, SM64);
    cudaFuncSetAttribute(feature_gemm<0>,  cudaFuncAttributeMaxDynamicSharedMemorySize, SMFEAT);
    cudaFuncSetAttribute(feature_gemm<1>,  cudaFuncAttributeMaxDynamicSharedMemorySize, SMFEAT);

    // 0) splits
    split_kernel<<<(BNc * Dc + 255) / 256, 256>>>(x, pxh, pxl, BNc * Dc, 1.0f);
    split_kernel<<<(Dc * Dc + 255) / 256, 256>>>(Wq, pwch, pwcl, Dc * Dc, 1.0f);
    split_kernel<<<(Dc * Dc + 255) / 256, 256>>>(Wk, pwch + Dc * Dc, pwcl + Dc * Dc, Dc * Dc, 1.0f);
    split_kernel<<<(Dc * Dc + 255) / 256, 256>>>(Wv, pwch + 2 * Dc * Dc, pwcl + 2 * Dc * Dc, Dc * Dc, 1.0f);
    split_kernel<<<(Dc * Dc + 255) / 256, 256>>>(Wo, pwoh, pwol, Dc * Dc, 1.0f);
    split_kernel<<<(Mc * DHc + 255) / 256, 256>>>(proj, pprh, pprl, Mc * DHc, DNf);  // fold dn
    bias_cat<<<1, Dc>>>(bq, bk, bv);

    // 1) fused QKV projection (single GEMM over [2304 x 768] weights)
    gemm_mma<128, 1><<<dim3(18, 128), 256, SM128>>>(pxh, pxl, pwch, pwcl, Dc, 30,
        pbcat, nullptr, nullptr, nullptr, 0);

    // 2) v transpose (independent of k/q feature path)
    transpose_split<<<dim3(DHc / 32, Nc / 32, BHc), 256>>>(pv, pvTh, pvTl, Nc, DHc);

    // 3) key feature GEMM -> raw xp (in qp buffers) + per-CTA max + diag
    feature_gemm<0><<<BHNc / 128, 512, SMFEAT>>>(pkh, pkl, pqph, pqpl);
    kmax_reduce<<<BHc, 32>>>();

    // 4) fused key finalize + transpose + ksum partials; reduce ksum
    kfin_transpose<<<dim3(Mc / 32, Nc / 32, BHc), 256>>>(pqph, pqpl);
    ksum_reduce<<<BHc, Mc>>>();

    // 5) query feature GEMM: exp + dinv fused, qp pre-scaled by dinv
    feature_gemm<1><<<BHNc / 128, 512, SMFEAT>>>(pqh, pql, pqph, pqpl);

    // 6) ctx per head = kpT @ vT^T -> ctxT bf16 splits
    gemm_mma<64, 3><<<dim3(1, BHc * 2), 256, SM64>>>(pkpTh, pkpTl, pvTh, pvTl, Nc, 8,
        nullptr, nullptr, pcxh, pcxl, DHc);

    // 7) out = qp_scaled @ ctxT^T -> merged-head bf16 splits
    gemm_mma<64, 2><<<dim3(1, BHNc / 128), 256, SM64>>>(pqph, pqpl, pcxh, pcxl, Mc, 11,
        nullptr, nullptr, path, patl, Dc);

    // 8) final output projection
    gemm_mma<128, 0><<<dim3(6, 128), 256, SM128>>>(path, patl, pwoh, pwol, Dc, 30,
        bo, out, nullptr, nullptr, Dc);
}

// round 17
// speedup vs baseline: 4.9474x; 1.3302x over previous
#include <cuda_runtime.h>
#include <cuda_bf16.h>
#include <math.h>
#include <stdint.h>

// ---------------------------------------------------------------------------
// Problem constants
// ---------------------------------------------------------------------------
#define Bc   8
#define Nc   2048
#define Dc   768
#define Hc   12
#define DHc  64
#define Mc   256
#define BHc  (Bc * Hc)      // 96
#define BHNc (BHc * Nc)     // 196608
#define BNc  (Bc * Nc)      // 16384

#define DNf    0.3535533905932738f   // 64^-0.25
#define DN2f   0.125f
#define RATIOf 0.0625f
#define EPSf   1e-4f
#define BEPSf  (RATIOf * EPSf)

// ---------------------------------------------------------------------------
// Device scratch
// ---------------------------------------------------------------------------
__device__ float g_v    [(size_t)BHNc * DHc];           // fp32 v, head-split
__device__ float g_ksum [(size_t)BHc * Mc];
__device__ float g_kspart[(size_t)BHc * 16 * Mc];       // per-CTA u column sums
__device__ float g_kpart[1536];                         // per-CTA xp max
__device__ float g_afac [BHc];                          // ratio * exp(-kmax)
__device__ float g_vsp  [(size_t)BHc * 64 * DHc];       // v column-sum partials
__device__ float g_vsum [(size_t)BHc * DHc];            // sum_n v
__device__ float g_bcat [3 * Dc];

__device__ __align__(128) __nv_bfloat16 g_xh [(size_t)BNc * Dc],  g_xl [(size_t)BNc * Dc];
__device__ __align__(128) __nv_bfloat16 g_wch[3 * Dc * Dc], g_wcl[3 * Dc * Dc];   // Wq|Wk|Wv
__device__ __align__(128) __nv_bfloat16 g_woh[Dc * Dc], g_wol[Dc * Dc];
__device__ __align__(128) __nv_bfloat16 g_prh[Mc * DHc], g_prl[Mc * DHc];          // dn * proj
__device__ __align__(128) __nv_bfloat16 g_qh [(size_t)BHNc * DHc], g_ql [(size_t)BHNc * DHc];
__device__ __align__(128) __nv_bfloat16 g_kh [(size_t)BHNc * DHc], g_kl [(size_t)BHNc * DHc];
__device__ __align__(128) __nv_bfloat16 g_kpTh[(size_t)BHNc * Mc], g_kpTl[(size_t)BHNc * Mc]; // uT [bh][m][n]
__device__ __align__(128) __nv_bfloat16 g_vTh[(size_t)BHNc * DHc], g_vTl[(size_t)BHNc * DHc]; // [bh][d][n]
__device__ __align__(128) __nv_bfloat16 g_cxh[(size_t)BHc * DHc * Mc], g_cxl[(size_t)BHc * DHc * Mc];
__device__ __align__(128) __nv_bfloat16 g_ath[(size_t)BNc * Dc], g_atl[(size_t)BNc * Dc];

// ---------------------------------------------------------------------------
// PTX helpers
// ---------------------------------------------------------------------------
__device__ __forceinline__ uint32_t smem_u32(const void* p) {
    uint32_t a;
    asm("{ .reg .u64 t; cvta.to.shared.u64 t, %1; cvt.u32.u64 %0, t; }"
        : "=r"(a) : "l"(p));
    return a;
}
__device__ __forceinline__ void cpa16(uint32_t s, const void* g) {
    asm volatile("cp.async.cg.shared.global [%0], [%1], 16;" :: "r"(s), "l"(g));
}
#define CP_COMMIT() asm volatile("cp.async.commit_group;" ::: "memory")
#define CP_WAIT0()  asm volatile("cp.async.wait_group 0;" ::: "memory")
#define CP_WAIT1()  asm volatile("cp.async.wait_group 1;" ::: "memory")

__device__ __forceinline__ void ldsm4(uint32_t* r, uint32_t addr) {
    asm volatile("ldmatrix.sync.aligned.m8n8.x4.shared.b16 {%0,%1,%2,%3}, [%4];"
                 : "=r"(r[0]), "=r"(r[1]), "=r"(r[2]), "=r"(r[3]) : "r"(addr));
}
__device__ __forceinline__ void mma16816(float* c, const uint32_t* a,
                                         uint32_t b0, uint32_t b1) {
    asm volatile(
        "mma.sync.aligned.m16n8k16.row.col.f32.bf16.bf16.f32 "
        "{%0,%1,%2,%3}, {%4,%5,%6,%7}, {%8,%9}, {%0,%1,%2,%3};"
        : "+f"(c[0]), "+f"(c[1]), "+f"(c[2]), "+f"(c[3])
        : "r"(a[0]), "r"(a[1]), "r"(a[2]), "r"(a[3]), "r"(b0), "r"(b1));
}
__device__ __forceinline__ void bfsplit(float v, __nv_bfloat16& h, __nv_bfloat16& l) {
    h = __float2bfloat16(v);
    l = __float2bfloat16(v - __bfloat162float(h));
}

// ---------------------------------------------------------------------------
// Split-precision bf16 mma.sync GEMM:  C = A @ B^T (+bias), fp32 acc, 3 passes
//   MODE 0: plain fp32 out [row*Nout+col] + bias       (final projection)
//   MODE 1: QKV-cat: col selects Wq/Wk/Wv; head-split; q/k -> bf16 splits, v fp32
//   MODE 3: ctx: val = afac[bh]*acc + BEPS*vsum[bh][col]; bf16 -> ctxT[(bh*64+col)*256+m]
// ---------------------------------------------------------------------------
template <int NTILE, int MODE>
__global__ void __launch_bounds__(256)
gemm_mma(const __nv_bfloat16* __restrict__ Ah, const __nv_bfloat16* __restrict__ Al,
         const __nv_bfloat16* __restrict__ Bh, const __nv_bfloat16* __restrict__ Bl,
         int K, int rowsLog2,
         const float* __restrict__ bias,
         const float* __restrict__ afac, const float* __restrict__ vsum,
         float* __restrict__ out32,
         __nv_bfloat16* __restrict__ outHi, __nv_bfloat16* __restrict__ outLo,
         int Nout)
{
    extern __shared__ __align__(128) char smem_raw[];
    const uint32_t smemBase = smem_u32(smem_raw);

    constexpr int OFF_AL = 16384;
    constexpr int OFF_BH = 32768;
    constexpr int OFF_BL = 32768 + NTILE * 128;
    constexpr int STAGE  = 32768 + NTILE * 256;

    const int tid  = threadIdx.x;
    const int wid  = tid >> 5;
    const int lane = tid & 31;
    const int rowBase = blockIdx.y * 128;
    const int colBase = blockIdx.x * NTILE;
    const int bhB = rowBase >> rowsLog2;

    const __nv_bfloat16* Bh2 = Bh + (size_t)bhB * NTILE * K;
    const __nv_bfloat16* Bl2 = Bl + (size_t)bhB * NTILE * K;

    constexpr int MT = (NTILE == 128) ? 4 : 2;
    const int mWarp = (NTILE == 128) ? (wid >> 2) * 64 : (wid >> 1) * 32;
    const int nWarp = (NTILE == 128) ? (wid & 3) * 32 : (wid & 1) * 32;

    const int l7 = lane & 7, gg = lane >> 3;
    const int aRowOff = l7 + ((gg & 1) << 3);
    const int aBit    = gg >> 1;
    const int bRowOff = l7 + ((gg >> 1) << 3);
    const int bBit    = gg & 1;

    uint32_t aRow[MT]; int aXor[MT];
#pragma unroll
    for (int mt = 0; mt < MT; mt++) {
        const int r = mWarp + mt * 16 + aRowOff;
        aRow[mt] = (uint32_t)(r * 128);
        aXor[mt] = r & 7;
    }
    uint32_t bRow[2]; int bXor[2];
#pragma unroll
    for (int g = 0; g < 2; g++) {
        const int r = nWarp + g * 16 + bRowOff;
        bRow[g] = (uint32_t)(r * 128);
        bXor[g] = r & 7;
    }

    float acc[MT][4][4];
#pragma unroll
    for (int mt = 0; mt < MT; mt++)
#pragma unroll
        for (int nt = 0; nt < 4; nt++)
#pragma unroll
            for (int e = 0; e < 4; e++) acc[mt][nt][e] = 0.f;

    const int nChunks = K >> 6;

    auto load_stage = [&](int c) {
        const uint32_t sd = smemBase + (uint32_t)((c & 1) * STAGE);
        const int kOff = c << 6;
#pragma unroll
        for (int f = tid; f < 1024; f += 256) {
            const int r = f >> 3, i = f & 7;
            const uint32_t sw = (uint32_t)(r * 128 + ((i ^ (r & 7)) << 4));
            const size_t g = (size_t)(rowBase + r) * K + kOff + i * 8;
            cpa16(sd + sw, Ah + g);
            cpa16(sd + OFF_AL + sw, Al + g);
        }
#pragma unroll
        for (int f = tid; f < NTILE * 8; f += 256) {
            const int r = f >> 3, i = f & 7;
            const uint32_t sw = (uint32_t)(r * 128 + ((i ^ (r & 7)) << 4));
            const size_t g = (size_t)(colBase + r) * K + kOff + i * 8;
            cpa16(sd + OFF_BH + sw, Bh2 + g);
            cpa16(sd + OFF_BL + sw, Bl2 + g);
        }
    };

    load_stage(0);
    CP_COMMIT();

    for (int c = 0; c < nChunks; c++) {
        if (c + 1 < nChunks) { load_stage(c + 1); CP_COMMIT(); CP_WAIT1(); }
        else                 { CP_WAIT0(); }
        __syncthreads();

        const uint32_t sb = smemBase + (uint32_t)((c & 1) * STAGE);
#pragma unroll
        for (int ks = 0; ks < 4; ks++) {
            uint32_t a_h[MT][4], a_l[MT][4];
#pragma unroll
            for (int mt = 0; mt < MT; mt++) {
                const uint32_t ad = sb + aRow[mt]
                    + (uint32_t)((((ks << 1) | aBit) ^ aXor[mt]) << 4);
                ldsm4(a_h[mt], ad);
                ldsm4(a_l[mt], ad + OFF_AL);
            }
            uint32_t b_h[2][4], b_l[2][4];
#pragma unroll
            for (int g = 0; g < 2; g++) {
                const uint32_t bd = sb + OFF_BH + bRow[g]
                    + (uint32_t)((((ks << 1) | bBit) ^ bXor[g]) << 4);
                ldsm4(b_h[g], bd);
                ldsm4(b_l[g], bd + (uint32_t)(NTILE * 128));
            }
#pragma unroll
            for (int mt = 0; mt < MT; mt++)
#pragma unroll
                for (int g = 0; g < 2; g++) {
                    mma16816(acc[mt][2*g],   a_h[mt], b_h[g][0], b_h[g][1]);
                    mma16816(acc[mt][2*g+1], a_h[mt], b_h[g][2], b_h[g][3]);
                    mma16816(acc[mt][2*g],   a_h[mt], b_l[g][0], b_l[g][1]);
                    mma16816(acc[mt][2*g+1], a_h[mt], b_l[g][2], b_l[g][3]);
                    mma16816(acc[mt][2*g],   a_l[mt], b_h[g][0], b_h[g][1]);
                    mma16816(acc[mt][2*g+1], a_l[mt], b_h[g][2], b_h[g][3]);
                }
        }
        __syncthreads();
    }

    const int lq = lane >> 2;
    const int lr = (lane & 3) * 2;

    auto emit = [&](int row, int col, float v) {
        if (MODE == 0) {
            out32[(size_t)row * Nout + col] = v + bias[col];
        } else if (MODE == 1) {
            const int mat = col / Dc;
            const int c = col - mat * Dc;
            const int h = c >> 6, dd = c & 63;
            const int bb = row >> 11, n = row & 2047;
            const float o = v + bias[col];
            const size_t idx = (((size_t)(bb * Hc + h) * Nc + n) << 6) + dd;
            if (mat == 0)      bfsplit(o, g_qh[idx], g_ql[idx]);
            else if (mat == 1) bfsplit(o, g_kh[idx], g_kl[idx]);
            else               g_v[idx] = o;
        } else { // MODE 3
            const int bh3 = row >> rowsLog2;
            const int m = row & ((1 << rowsLog2) - 1);
            const float o = afac[bh3] * v + BEPSf * vsum[bh3 * DHc + col];
            const size_t idx = ((size_t)(bh3 * DHc + col)) * Mc + m;
            bfsplit(o, outHi[idx], outLo[idx]);
        }
    };

#pragma unroll
    for (int mt = 0; mt < MT; mt++)
#pragma unroll
        for (int nt = 0; nt < 4; nt++) {
            const int row = rowBase + mWarp + mt * 16 + lq;
            const int col = colBase + nWarp + nt * 8 + lr;
            emit(row,     col,     acc[mt][nt][0]);
            emit(row,     col + 1, acc[mt][nt][1]);
            emit(row + 8, col,     acc[mt][nt][2]);
            emit(row + 8, col + 1, acc[mt][nt][3]);
        }
}

// ---------------------------------------------------------------------------
// Key feature kernel: u = exp(xp - diag) without max (fp32-safe), writes
// uT [bh][m][n] bf16 hi/lo (transposed through smem), per-CTA xp max,
// per-CTA column sums of u (ksum partials).
// tile 128(n) x 256(m), K=64, 512 threads.
// ---------------------------------------------------------------------------
__global__ void __launch_bounds__(512)
feature_k(const __nv_bfloat16* __restrict__ Ah, const __nv_bfloat16* __restrict__ Al)
{
    extern __shared__ __align__(128) char smem_raw[];
    const uint32_t sb = smem_u32(smem_raw);
    __shared__ float sdiag[128];
    __shared__ float scol[4][256];
    __shared__ float smax[16];

    const int tid  = threadIdx.x;
    const int wid  = tid >> 5;
    const int lane = tid & 31;
    const int rowBase = blockIdx.x * 128;
    const int bh   = blockIdx.x >> 4;
    const int ctaN = blockIdx.x & 15;

    const int mWarp = (wid >> 2) * 32;
    const int warpN = wid & 3;
    const int nWarp = warpN * 64;

    // ---- load A (k splits) + proj ----
#pragma unroll
    for (int f = tid; f < 1024; f += 512) {
        const int r = f >> 3, i = f & 7;
        const uint32_t sw = (uint32_t)(r * 128 + ((i ^ (r & 7)) << 4));
        const size_t g = (size_t)(rowBase + r) * DHc + i * 8;
        cpa16(sb + sw, Ah + g);
        cpa16(sb + 16384 + sw, Al + g);
    }
#pragma unroll
    for (int f = tid; f < 2048; f += 512) {
        const int r = f >> 3, i = f & 7;
        const uint32_t sw = (uint32_t)(r * 128 + ((i ^ (r & 7)) << 4));
        const size_t g = (size_t)r * DHc + i * 8;
        cpa16(sb + 32768 + sw, g_prh + g);
        cpa16(sb + 65536 + sw, g_prl + g);
    }
    CP_COMMIT(); CP_WAIT0();
    __syncthreads();

    const int l7 = lane & 7, gg = lane >> 3;
    const int aRowOff = l7 + ((gg & 1) << 3);
    const int aBit    = gg >> 1;
    const int bRowOff = l7 + ((gg >> 1) << 3);
    const int bBit    = gg & 1;

    float acc[2][8][4];
#pragma unroll
    for (int mt = 0; mt < 2; mt++)
#pragma unroll
        for (int nt = 0; nt < 8; nt++)
#pragma unroll
            for (int e = 0; e < 4; e++) acc[mt][nt][e] = 0.f;

#pragma unroll
    for (int ks = 0; ks < 4; ks++) {
        uint32_t a_h[2][4], a_l[2][4];
#pragma unroll
        for (int mt = 0; mt < 2; mt++) {
            const int ar = mWarp + mt * 16 + aRowOff;
            const uint32_t ad = sb + (uint32_t)(ar * 128)
                + (uint32_t)((((ks << 1) | aBit) ^ (ar & 7)) << 4);
            ldsm4(a_h[mt], ad);
            ldsm4(a_l[mt], ad + 16384);
        }
#pragma unroll
        for (int g = 0; g < 4; g++) {
            const int br = nWarp + g * 16 + bRowOff;
            const uint32_t bd = sb + 32768 + (uint32_t)(br * 128)
                + (uint32_t)((((ks << 1) | bBit) ^ (br & 7)) << 4);
            uint32_t b_h[4], b_l[4];
            ldsm4(b_h, bd);
            ldsm4(b_l, bd + 32768);
#pragma unroll
            for (int mt = 0; mt < 2; mt++) {
                mma16816(acc[mt][2*g],   a_h[mt], b_h[0], b_h[1]);
                mma16816(acc[mt][2*g+1], a_h[mt], b_h[2], b_h[3]);
                mma16816(acc[mt][2*g],   a_h[mt], b_l[0], b_l[1]);
                mma16816(acc[mt][2*g+1], a_h[mt], b_l[2], b_l[3]);
                mma16816(acc[mt][2*g],   a_l[mt], b_h[0], b_h[1]);
                mma16816(acc[mt][2*g+1], a_l[mt], b_h[2], b_h[3]);
            }
        }
    }

    // ---- diag from A smem ----
    {
        const int r = tid >> 2, p = tid & 3;
        float s = 0.f;
#pragma unroll
        for (int e = 0; e < 16; e++) {
            const int k = p * 16 + e;
            const uint32_t off = (uint32_t)(r * 128 + (((k >> 3) ^ (r & 7)) << 4) + (k & 7) * 2);
            const float hv = __bfloat162float(*(const __nv_bfloat16*)(smem_raw + off));
            const float lv = __bfloat162float(*(const __nv_bfloat16*)(smem_raw + 16384 + off));
            const float v = hv + lv;
            s += v * v;
        }
        s += __shfl_xor_sync(0xffffffffu, s, 1);
        s += __shfl_xor_sync(0xffffffffu, s, 2);
        if (p == 0) sdiag[r] = 0.5f * DN2f * s;
    }
    __syncthreads();

    const int lq = lane >> 2;
    const int lr = (lane & 3) * 2;
    const int rowLoc0 = mWarp + lq;

    // ---- u = exp(xp - diag), per-CTA xp max ----
    float bm = -3.0e38f;
#pragma unroll
    for (int mt = 0; mt < 2; mt++) {
        const float dg0 = sdiag[rowLoc0 + mt * 16];
        const float dg1 = sdiag[rowLoc0 + mt * 16 + 8];
#pragma unroll
        for (int nt = 0; nt < 8; nt++)
#pragma unroll
            for (int e = 0; e < 4; e++) {
                const float xp = acc[mt][nt][e];
                bm = fmaxf(bm, xp);
                acc[mt][nt][e] = expf(xp - ((e >> 1) ? dg1 : dg0));
            }
    }
#pragma unroll
    for (int o = 16; o > 0; o >>= 1)
        bm = fmaxf(bm, __shfl_xor_sync(0xffffffffu, bm, o));
    if (lane == 0) smax[wid] = bm;

    // ---- column sums of u (over this CTA's 128 n) ----
    {
        float cs[8][2];
#pragma unroll
        for (int nt = 0; nt < 8; nt++) {
            cs[nt][0] = acc[0][nt][0] + acc[0][nt][2] + acc[1][nt][0] + acc[1][nt][2];
            cs[nt][1] = acc[0][nt][1] + acc[0][nt][3] + acc[1][nt][1] + acc[1][nt][3];
        }
#pragma unroll
        for (int nt = 0; nt < 8; nt++)
#pragma unroll
            for (int j = 0; j < 2; j++) {
                cs[nt][j] += __shfl_xor_sync(0xffffffffu, cs[nt][j], 4);
                cs[nt][j] += __shfl_xor_sync(0xffffffffu, cs[nt][j], 8);
                cs[nt][j] += __shfl_xor_sync(0xffffffffu, cs[nt][j], 16);
            }
        if (lane < 4) {
#pragma unroll
            for (int nt = 0; nt < 8; nt++) {
                scol[wid >> 2][nWarp + nt * 8 + lr]     = cs[nt][0];
                scol[wid >> 2][nWarp + nt * 8 + lr + 1] = cs[nt][1];
            }
        }
    }
    __syncthreads();
    if (tid < 256)
        g_kspart[((size_t)bh * 16 + ctaN) * Mc + tid] =
            scol[0][tid] + scol[1][tid] + scol[2][tid] + scol[3][tid];
    if (tid == 0) {
        float mm = smax[0];
#pragma unroll
        for (int i = 1; i < 16; i++) mm = fmaxf(mm, smax[i]);
        g_kpart[blockIdx.x] = mm;
    }

    // ---- transpose u through smem (two 128-m halves), write uT hi/lo ----
    const int STR = 136;                  // padded row stride (elements)
    __nv_bfloat16* th = (__nv_bfloat16*)smem_raw;
    __nv_bfloat16* tl = (__nv_bfloat16*)(smem_raw + 128 * STR * 2);

#pragma unroll
    for (int h = 0; h < 2; h++) {
        __syncthreads();
        if ((warpN >> 1) == h) {
            const int mBase = (warpN & 1) * 64;
#pragma unroll
            for (int mt = 0; mt < 2; mt++)
#pragma unroll
                for (int nt = 0; nt < 8; nt++)
#pragma unroll
                    for (int e = 0; e < 4; e++) {
                        const int n = rowLoc0 + mt * 16 + (e >> 1) * 8;
                        const int m = mBase + nt * 8 + lr + (e & 1);
                        bfsplit(acc[mt][nt][e], th[m * STR + n], tl[m * STR + n]);
                    }
        }
        __syncthreads();
        const int mLoc = tid >> 2;
        const int n0 = (tid & 3) * 32;
        const size_t grow = ((size_t)(bh * Mc + h * 128 + mLoc)) * Nc + ctaN * 128 + n0;
#pragma unroll
        for (int ii = 0; ii < 4; ii++) {
            const int eo = mLoc * STR + n0 + ii * 8;
            *(float4*)(g_kpTh + grow + ii * 8) = *(const float4*)(th + eo);
            *(float4*)(g_kpTl + grow + ii * 8) = *(const float4*)(tl + eo);
        }
    }
}

// ---------------------------------------------------------------------------
// kmax -> afac ; ksum = afac*sum_u + ratio*eps*N ; vsum reduce
// ---------------------------------------------------------------------------
__global__ void kmax_afac()
{
    const int bh = blockIdx.x, lane = threadIdx.x;
    float v = (lane < 16) ? g_kpart[bh * 16 + lane] : -3.0e38f;
#pragma unroll
    for (int o = 16; o > 0; o >>= 1)
        v = fmaxf(v, __shfl_xor_sync(0xffffffffu, v, o));
    if (lane == 0) g_afac[bh] = RATIOf * expf(-v);
}

__global__ void __launch_bounds__(256)
ksum_reduce()
{
    const int bh = blockIdx.x, m = threadIdx.x;
    float s = 0.f;
#pragma unroll
    for (int i = 0; i < 16; i++)
        s += g_kspart[((size_t)bh * 16 + i) * Mc + m];
    g_ksum[bh * Mc + m] = g_afac[bh] * s + BEPSf * (float)Nc;
}

__global__ void vsum_reduce()
{
    const int bh = blockIdx.x, d = threadIdx.x;
    float s = 0.f;
#pragma unroll 8
    for (int i = 0; i < 64; i++)
        s += g_vsp[((size_t)bh * 64 + i) * DHc + d];
    g_vsum[bh * DHc + d] = s;
}

// ---------------------------------------------------------------------------
// Fused query feature + out GEMM.
// Phase 1: qp = ratio*(exp(q.projT - diag - rowmax) + eps), dinv folded.
// Phase 2: out = qp @ ctxT^T (ctx resident in smem), writes g_ath/g_atl.
// ---------------------------------------------------------------------------
__global__ void __launch_bounds__(512)
query_out(const __nv_bfloat16* __restrict__ Ah, const __nv_bfloat16* __restrict__ Al)
{
    extern __shared__ __align__(128) char smem_raw[];
    const uint32_t sb = smem_u32(smem_raw);
    __shared__ float sred[4][128];
    __shared__ float sdiag[128];

    const int tid  = threadIdx.x;
    const int wid  = tid >> 5;
    const int lane = tid & 31;
    const int rowBase = blockIdx.x * 128;
    const int bh = rowBase >> 11;

    const int mWarp = (wid >> 2) * 32;
    const int warpN = wid & 3;
    const int nWarp = warpN * 64;

    // ---- load q splits + proj ----
#pragma unroll
    for (int f = tid; f < 1024; f += 512) {
        const int r = f >> 3, i = f & 7;
        const uint32_t sw = (uint32_t)(r * 128 + ((i ^ (r & 7)) << 4));
        const size_t g = (size_t)(rowBase + r) * DHc + i * 8;
        cpa16(sb + sw, Ah + g);
        cpa16(sb + 16384 + sw, Al + g);
    }
#pragma unroll
    for (int f = tid; f < 2048; f += 512) {
        const int r = f >> 3, i = f & 7;
        const uint32_t sw = (uint32_t)(r * 128 + ((i ^ (r & 7)) << 4));
        const size_t g = (size_t)r * DHc + i * 8;
        cpa16(sb + 32768 + sw, g_prh + g);
        cpa16(sb + 65536 + sw, g_prl + g);
    }
    CP_COMMIT(); CP_WAIT0();
    __syncthreads();

    const int l7 = lane & 7, gg = lane >> 3;
    const int aRowOff = l7 + ((gg & 1) << 3);
    const int aBit    = gg >> 1;
    const int bRowOff = l7 + ((gg >> 1) << 3);
    const int bBit    = gg & 1;

    float acc[2][8][4];
#pragma unroll
    for (int mt = 0; mt < 2; mt++)
#pragma unroll
        for (int nt = 0; nt < 8; nt++)
#pragma unroll
            for (int e = 0; e < 4; e++) acc[mt][nt][e] = 0.f;

#pragma unroll
    for (int ks = 0; ks < 4; ks++) {
        uint32_t a_h[2][4], a_l[2][4];
#pragma unroll
        for (int mt = 0; mt < 2; mt++) {
            const int ar = mWarp + mt * 16 + aRowOff;
            const uint32_t ad = sb + (uint32_t)(ar * 128)
                + (uint32_t)((((ks << 1) | aBit) ^ (ar & 7)) << 4);
            ldsm4(a_h[mt], ad);
            ldsm4(a_l[mt], ad + 16384);
        }
#pragma unroll
        for (int g = 0; g < 4; g++) {
            const int br = nWarp + g * 16 + bRowOff;
            const uint32_t bd = sb + 32768 + (uint32_t)(br * 128)
                + (uint32_t)((((ks << 1) | bBit) ^ (br & 7)) << 4);
            uint32_t b_h[4], b_l[4];
            ldsm4(b_h, bd);
            ldsm4(b_l, bd + 32768);
#pragma unroll
            for (int mt = 0; mt < 2; mt++) {
                mma16816(acc[mt][2*g],   a_h[mt], b_h[0], b_h[1]);
                mma16816(acc[mt][2*g+1], a_h[mt], b_h[2], b_h[3]);
                mma16816(acc[mt][2*g],   a_h[mt], b_l[0], b_l[1]);
                mma16816(acc[mt][2*g+1], a_h[mt], b_l[2], b_l[3]);
                mma16816(acc[mt][2*g],   a_l[mt], b_h[0], b_h[1]);
                mma16816(acc[mt][2*g+1], a_l[mt], b_h[2], b_h[3]);
            }
        }
    }
    __syncthreads();   // all warps done reading proj region

    // ---- start ctx B load (overwrites proj region) ----
#pragma unroll
    for (int f = tid; f < 2048; f += 512) {
        const int r = f >> 5, i = f & 31;
        const int c = i >> 3, il = i & 7;
        const uint32_t ad = sb + 32768 + (uint32_t)(c * 16384 + r * 128 + ((il ^ (r & 7)) << 4));
        const size_t g = ((size_t)(bh * DHc + r)) * Mc + i * 8;
        cpa16(ad, g_cxh + g);
        cpa16(ad + 8192, g_cxl + g);
    }
    CP_COMMIT();

    // ---- diag from A smem (region untouched) ----
    {
        const int r = tid >> 2, p = tid & 3;
        float s = 0.f;
#pragma unroll
        for (int e = 0; e < 16; e++) {
            const int k = p * 16 + e;
            const uint32_t off = (uint32_t)(r * 128 + (((k >> 3) ^ (r & 7)) << 4) + (k & 7) * 2);
            const float hv = __bfloat162float(*(const __nv_bfloat16*)(smem_raw + off));
            const float lv = __bfloat162float(*(const __nv_bfloat16*)(smem_raw + 16384 + off));
            const float v = hv + lv;
            s += v * v;
        }
        s += __shfl_xor_sync(0xffffffffu, s, 1);
        s += __shfl_xor_sync(0xffffffffu, s, 2);
        if (p == 0) sdiag[r] = 0.5f * DN2f * s;
    }
    __syncthreads();

    const int lq = lane >> 2;
    const int lr = (lane & 3) * 2;
    const int rowLoc0 = mWarp + lq;

    // ---- row max ----
    float m_[2][2];
#pragma unroll
    for (int mt = 0; mt < 2; mt++) {
        float m0 = -3.0e38f, m1 = -3.0e38f;
#pragma unroll
        for (int nt = 0; nt < 8; nt++) {
            m0 = fmaxf(m0, fmaxf(acc[mt][nt][0], acc[mt][nt][1]));
            m1 = fmaxf(m1, fmaxf(acc[mt][nt][2], acc[mt][nt][3]));
        }
        m_[mt][0] = m0; m_[mt][1] = m1;
    }
#pragma unroll
    for (int mt = 0; mt < 2; mt++)
#pragma unroll
        for (int hf = 0; hf < 2; hf++) {
            m_[mt][hf] = fmaxf(m_[mt][hf], __shfl_xor_sync(0xffffffffu, m_[mt][hf], 1));
            m_[mt][hf] = fmaxf(m_[mt][hf], __shfl_xor_sync(0xffffffffu, m_[mt][hf], 2));
        }
    if ((lane & 3) == 0) {
#pragma unroll
        for (int mt = 0; mt < 2; mt++) {
            sred[warpN][rowLoc0 + mt * 16]     = m_[mt][0];
            sred[warpN][rowLoc0 + mt * 16 + 8] = m_[mt][1];
        }
    }
    __syncthreads();
    float mx[2][2], dgv[2][2];
#pragma unroll
    for (int mt = 0; mt < 2; mt++)
#pragma unroll
        for (int hf = 0; hf < 2; hf++) {
            const int row = rowLoc0 + mt * 16 + hf * 8;
            mx[mt][hf] = fmaxf(fmaxf(sred[0][row], sred[1][row]),
                               fmaxf(sred[2][row], sred[3][row]));
            dgv[mt][hf] = sdiag[row];
        }
    __syncthreads();

    // ---- exp + dot with ksum ----
    float dot[2][2] = {{0.f, 0.f}, {0.f, 0.f}};
#pragma unroll
    for (int mt = 0; mt < 2; mt++)
#pragma unroll
        for (int nt = 0; nt < 8; nt++) {
            const int col = nWarp + nt * 8 + lr;
            const float k0 = g_ksum[bh * Mc + col];
            const float k1 = g_ksum[bh * Mc + col + 1];
#pragma unroll
            for (int e = 0; e < 4; e++) {
                const int hf = e >> 1;
                const float v = RATIOf *
                    (expf(acc[mt][nt][e] - dgv[mt][hf] - mx[mt][hf]) + EPSf);
                acc[mt][nt][e] = v;
                dot[mt][hf] += v * ((e & 1) ? k1 : k0);
            }
        }
#pragma unroll
    for (int mt = 0; mt < 2; mt++)
#pragma unroll
        for (int hf = 0; hf < 2; hf++) {
            dot[mt][hf] += __shfl_xor_sync(0xffffffffu, dot[mt][hf], 1);
            dot[mt][hf] += __shfl_xor_sync(0xffffffffu, dot[mt][hf], 2);
        }
    if ((lane & 3) == 0) {
#pragma unroll
        for (int mt = 0; mt < 2; mt++) {
            sred[warpN][rowLoc0 + mt * 16]     = dot[mt][0];
            sred[warpN][rowLoc0 + mt * 16 + 8] = dot[mt][1];
        }
    }
    __syncthreads();
#pragma unroll
    for (int mt = 0; mt < 2; mt++)
#pragma unroll
        for (int hf = 0; hf < 2; hf++) {
            const int row = rowLoc0 + mt * 16 + hf * 8;
            const float dv = 1.0f / (sred[0][row] + sred[1][row]
                                   + sred[2][row] + sred[3][row]);
#pragma unroll
            for (int nt = 0; nt < 8; nt++) {
                acc[mt][nt][2*hf]   *= dv;
                acc[mt][nt][2*hf+1] *= dv;
            }
        }

    CP_WAIT0();
    __syncthreads();

    // ---- phase 2: out = qp @ ctxT^T, K=256 in 4 chunks of 64 ----
    __nv_bfloat16* sth = (__nv_bfloat16*)smem_raw;            // A stage hi (128x64)
    const int nWarp2 = warpN * 16;

    float acc2[2][2][4];
#pragma unroll
    for (int mt = 0; mt < 2; mt++)
#pragma unroll
        for (int nt = 0; nt < 2; nt++)
#pragma unroll
            for (int e = 0; e < 4; e++) acc2[mt][nt][e] = 0.f;

#pragma unroll
    for (int c = 0; c < 4; c++) {
        if (warpN == c) {
#pragma unroll
            for (int mt = 0; mt < 2; mt++)
#pragma unroll
                for (int nt = 0; nt < 8; nt++)
#pragma unroll
                    for (int e = 0; e < 4; e++) {
                        const int n = rowLoc0 + mt * 16 + (e >> 1) * 8;
                        const int k = nt * 8 + lr + (e & 1);
                        const uint32_t off = (uint32_t)(n * 128
                            + (((k >> 3) ^ (n & 7)) << 4) + (k & 7) * 2);
                        __nv_bfloat16 hv, lv;
                        bfsplit(acc[mt][nt][e], hv, lv);
                        *(__nv_bfloat16*)(smem_raw + off) = hv;
                        *(__nv_bfloat16*)(smem_raw + 16384 + off) = lv;
                    }
        }
        __syncthreads();

#pragma unroll
        for (int ks = 0; ks < 4; ks++) {
            uint32_t a_h[2][4], a_l[2][4];
#pragma unroll
            for (int mt = 0; mt < 2; mt++) {
                const int ar = mWarp + mt * 16 + aRowOff;
                const uint32_t ad = sb + (uint32_t)(ar * 128)
                    + (uint32_t)((((ks << 1) | aBit) ^ (ar & 7)) << 4);
                ldsm4(a_h[mt], ad);
                ldsm4(a_l[mt], ad + 16384);
            }
            const int br = nWarp2 + bRowOff;
            const uint32_t bd = sb + 32768 + (uint32_t)(c * 16384 + br * 128)
                + (uint32_t)((((ks << 1) | bBit) ^ (br & 7)) << 4);
            uint32_t b_h[4], b_l[4];
            ldsm4(b_h, bd);
            ldsm4(b_l, bd + 8192);
#pragma unroll
            for (int mt = 0; mt < 2; mt++) {
                mma16816(acc2[mt][0], a_h[mt], b_h[0], b_h[1]);
                mma16816(acc2[mt][1], a_h[mt], b_h[2], b_h[3]);
                mma16816(acc2[mt][0], a_h[mt], b_l[0], b_l[1]);
                mma16816(acc2[mt][1], a_h[mt], b_l[2], b_l[3]);
                mma16816(acc2[mt][0], a_l[mt], b_h[0], b_h[1]);
                mma16816(acc2[mt][1], a_l[mt], b_h[2], b_h[3]);
            }
        }
        __syncthreads();
    }
    (void)sth;

    // ---- epilogue: rows -> (b,n), cols -> d ----
    const int b = bh / Hc, h = bh % Hc;
#pragma unroll
    for (int mt = 0; mt < 2; mt++)
#pragma unroll
        for (int nt = 0; nt < 2; nt++) {
            const int row = rowBase + mWarp + mt * 16 + lq;
            const int col = nWarp2 + nt * 8 + lr;
#pragma unroll
            for (int e = 0; e < 4; e++) {
                const int rr = row + (e >> 1) * 8;
                const int cc = col + (e & 1);
                const int n = rr & 2047;
                const size_t idx = ((size_t)(b * Nc + n)) * Dc + h * 64 + cc;
                bfsplit(acc2[mt][nt][e], g_ath[idx], g_atl[idx]);
            }
        }
}

// ---------------------------------------------------------------------------
// fp32 -> bf16 hi/lo split (optional pre-scale)
// ---------------------------------------------------------------------------
__global__ void __launch_bounds__(256)
split_kernel(const float* __restrict__ src, __nv_bfloat16* __restrict__ h,
             __nv_bfloat16* __restrict__ l, int n, float scale)
{
    int i = blockIdx.x * 256 + threadIdx.x;
    if (i < n) bfsplit(src[i] * scale, h[i], l[i]);
}

__global__ void bias_cat(const float* bq, const float* bk, const float* bv)
{
    const int i = threadIdx.x;
    g_bcat[i] = bq[i];
    g_bcat[Dc + i] = bk[i];
    g_bcat[2 * Dc + i] = bv[i];
}

// ---------------------------------------------------------------------------
// v transpose + split + column-sum partials: [bh][n][64] -> [bh][64][n]
// ---------------------------------------------------------------------------
__global__ void __launch_bounds__(256)
transpose_v()
{
    __shared__ float t[32][33];
    const int bh = blockIdx.z;
    const size_t zb = (size_t)bh * Nc * DHc;
    const int r0 = blockIdx.y * 32, c0 = blockIdx.x * 32;
    const int tx = threadIdx.x & 31, ty = threadIdx.x >> 5;
#pragma unroll
    for (int i = 0; i < 4; i++)
        t[ty + i * 8][tx] = g_v[zb + (size_t)(r0 + ty + i * 8) * DHc + c0 + tx];
    __syncthreads();
#pragma unroll
    for (int i = 0; i < 4; i++) {
        const int cc = c0 + ty + i * 8;     // d
        const int rr = r0 + tx;             // n
        const float v = t[tx][ty + i * 8];
        const size_t idx = zb + (size_t)cc * Nc + rr;
        bfsplit(v, g_vTh[idx], g_vTl[idx]);
        float s = v;
#pragma unroll
        for (int o = 16; o > 0; o >>= 1)
            s += __shfl_xor_sync(0xffffffffu, s, o);
        if (tx == 0)
            g_vsp[((size_t)bh * 64 + blockIdx.y) * DHc + cc] = s;
    }
}

// ---------------------------------------------------------------------------
// Launch
// ---------------------------------------------------------------------------
extern "C" void kernel_launch(void* const* d_in, const int* in_sizes, int n_in,
                              void* d_out, int out_size)
{
    const float* x    = (const float*)d_in[0];
    const float* Wq   = (const float*)d_in[1];
    const float* bq   = (const float*)d_in[2];
    const float* Wk   = (const float*)d_in[3];
    const float* bk   = (const float*)d_in[4];
    const float* Wv   = (const float*)d_in[5];
    const float* bv   = (const float*)d_in[6];
    const float* Wo   = (const float*)d_in[7];
    const float* bo   = (const float*)d_in[8];
    const float* proj = (const float*)d_in[9];
    float* out = (float*)d_out;

    float *pbcat, *pafac, *pvsum;
    __nv_bfloat16 *pxh, *pxl, *pwch, *pwcl, *pwoh, *pwol, *pprh, *pprl,
                  *pqh, *pql, *pkh, *pkl,
                  *pkpTh, *pkpTl, *pvTh, *pvTl, *pcxh, *pcxl, *path, *patl;
    cudaGetSymbolAddress((void**)&pbcat, g_bcat);
    cudaGetSymbolAddress((void**)&pafac, g_afac);
    cudaGetSymbolAddress((void**)&pvsum, g_vsum);
    cudaGetSymbolAddress((void**)&pxh, g_xh);     cudaGetSymbolAddress((void**)&pxl, g_xl);
    cudaGetSymbolAddress((void**)&pwch, g_wch);   cudaGetSymbolAddress((void**)&pwcl, g_wcl);
    cudaGetSymbolAddress((void**)&pwoh, g_woh);   cudaGetSymbolAddress((void**)&pwol, g_wol);
    cudaGetSymbolAddress((void**)&pprh, g_prh);   cudaGetSymbolAddress((void**)&pprl, g_prl);
    cudaGetSymbolAddress((void**)&pqh, g_qh);     cudaGetSymbolAddress((void**)&pql, g_ql);
    cudaGetSymbolAddress((void**)&pkh, g_kh);     cudaGetSymbolAddress((void**)&pkl, g_kl);
    cudaGetSymbolAddress((void**)&pkpTh, g_kpTh); cudaGetSymbolAddress((void**)&pkpTl, g_kpTl);
    cudaGetSymbolAddress((void**)&pvTh, g_vTh);   cudaGetSymbolAddress((void**)&pvTl, g_vTl);
    cudaGetSymbolAddress((void**)&pcxh, g_cxh);   cudaGetSymbolAddress((void**)&pcxl, g_cxl);
    cudaGetSymbolAddress((void**)&path, g_ath);   cudaGetSymbolAddress((void**)&patl, g_atl);

    const int SM128 = 2 * (32768 + 128 * 256);   // 131072
    const int SM64  = 2 * (32768 + 64 * 256);    //  98304
    const int SMFEAT = 98304;
    cudaFuncSetAttribute(gemm_mma<128, 0>, cudaFuncAttributeMaxDynamicSharedMemorySize, SM128);
    cudaFuncSetAttribute(gemm_mma<128, 1>, cudaFuncAttributeMaxDynamicSharedMemorySize, SM128);
    cudaFuncSetAttribute(gemm_mma<64, 3>,  cudaFuncAttributeMaxDynamicSharedMemorySize, SM64);
    cudaFuncSetAttribute(feature_k,        cudaFuncAttributeMaxDynamicSharedMemorySize, SMFEAT);
    cudaFuncSetAttribute(query_out,        cudaFuncAttributeMaxDynamicSharedMemorySize, SMFEAT);

    // 0) splits
    split_kernel<<<(BNc * Dc + 255) / 256, 256>>>(x, pxh, pxl, BNc * Dc, 1.0f);
    split_kernel<<<(Dc * Dc + 255) / 256, 256>>>(Wq, pwch, pwcl, Dc * Dc, 1.0f);
    split_kernel<<<(Dc * Dc + 255) / 256, 256>>>(Wk, pwch + Dc * Dc, pwcl + Dc * Dc, Dc * Dc, 1.0f);
    split_kernel<<<(Dc * Dc + 255) / 256, 256>>>(Wv, pwch + 2 * Dc * Dc, pwcl + 2 * Dc * Dc, Dc * Dc, 1.0f);
    split_kernel<<<(Dc * Dc + 255) / 256, 256>>>(Wo, pwoh, pwol, Dc * Dc, 1.0f);
    split_kernel<<<(Mc * DHc + 255) / 256, 256>>>(proj, pprh, pprl, Mc * DHc, DNf);
    bias_cat<<<1, Dc>>>(bq, bk, bv);

    // 1) fused QKV projection
    gemm_mma<128, 1><<<dim3(18, 128), 256, SM128>>>(pxh, pxl, pwch, pwcl, Dc, 30,
        pbcat, nullptr, nullptr, nullptr, nullptr, nullptr, 0);

    // 2) v transpose + vsum partials
    transpose_v<<<dim3(2, 64, BHc), 256>>>();
    vsum_reduce<<<BHc, DHc>>>();

    // 3) key feature: u = exp(xp - diag), uT + ksum partials + per-CTA max
    feature_k<<<BHNc / 128, 512, SMFEAT>>>(pkh, pkl);
    kmax_afac<<<BHc, 32>>>();
    ksum_reduce<<<BHc, Mc>>>();

    // 4) ctx_u = uT @ vT^T ; epilogue: ctx = afac*ctx_u + beps*vsum
    gemm_mma<64, 3><<<dim3(1, BHc * 2), 256, SM64>>>(pkpTh, pkpTl, pvTh, pvTl, Nc, 8,
        nullptr, pafac, pvsum, nullptr, pcxh, pcxl, DHc);

    // 5) fused query feature + out GEMM (qp never leaves the SM)
    query_out<<<BHNc / 128, 512, SMFEAT>>>(pqh, pql);

    // 6) final output projection
    gemm_mma<128, 0><<<dim3(6, 128), 256, SM128>>>(path, patl, pwoh, pwol, Dc, 30,
        bo, nullptr, nullptr, out, nullptr, nullptr, Dc);
}